// round 1
// baseline (speedup 1.0000x reference)
#include <cuda_runtime.h>
#include <cuda_bf16.h>
#include <mma.h>

using namespace nvcuda;
typedef __nv_bfloat16 bf16;

#define NN   20000
#define DEGC 16
#define NE   (NN*DEGC)     // 320000
#define DIMC 128
#define SCALEC 0.25f       // HD^-0.5, HD=16

// ---------------- scratch (__device__ globals; no allocation allowed) ----------------
__device__ bf16  g_x_hi[NN*DIMC];
__device__ bf16  g_x_lo[NN*DIMC];
__device__ float g_Q [NN*DIMC];
__device__ float g_KS[NN*DIMC];
__device__ float g_V [NN*DIMC];
__device__ bf16  g_agg_hi[NN*DIMC];
__device__ bf16  g_agg_lo[NN*DIMC];
// weight slots: 0=Wq 1=Wk*SCALE 2=Wv 3=Wek*SCALE 4=Wev 5=-Wout
__device__ bf16  g_w_hi[6*DIMC*DIMC];
__device__ bf16  g_w_lo[6*DIMC*DIMC];

// ---------------- split fp32 -> bf16 hi/lo ----------------
__global__ void split_kernel(const float* __restrict__ src, bf16* __restrict__ hi,
                             bf16* __restrict__ lo, float scale, int n)
{
    int i = blockIdx.x*256 + threadIdx.x;
    if (i < n) {
        float v = src[i]*scale;
        bf16 h = __float2bfloat16(v);
        hi[i] = h;
        lo[i] = __float2bfloat16(v - __bfloat162float(h));
    }
}

// ---------------- shared 128x128 split-bf16 MMA tile (16 warps) ----------------
// A: [128 x 128] rows=edges/nodes (smem stride 136), B: [128 x 128] row-major k x n (stride 136)
// C: [128 x 132] fp32 smem
__device__ __forceinline__ void mma_128x128(const bf16* A_hi, const bf16* A_lo,
                                            const bf16* B_hi, const bf16* B_lo,
                                            float* Cout, int w)
{
    const int rt = w>>1;   // 0..7 : 16-row tile
    const int cg = w&1;    // 0..1 : 64-col group
    wmma::fragment<wmma::accumulator,16,16,16,float> acc[4];
    #pragma unroll
    for (int j=0;j<4;j++) wmma::fill_fragment(acc[j], 0.f);
    #pragma unroll
    for (int kk=0; kk<8; kk++) {
        wmma::fragment<wmma::matrix_a,16,16,16,bf16,wmma::row_major> ah, al;
        wmma::load_matrix_sync(ah, A_hi + rt*16*136 + kk*16, 136);
        wmma::load_matrix_sync(al, A_lo + rt*16*136 + kk*16, 136);
        #pragma unroll
        for (int ct=0; ct<4; ct++) {
            wmma::fragment<wmma::matrix_b,16,16,16,bf16,wmma::row_major> bh, bl;
            wmma::load_matrix_sync(bh, B_hi + kk*16*136 + cg*64 + ct*16, 136);
            wmma::load_matrix_sync(bl, B_lo + kk*16*136 + cg*64 + ct*16, 136);
            wmma::mma_sync(acc[ct], ah, bh, acc[ct]);
            wmma::mma_sync(acc[ct], ah, bl, acc[ct]);
            wmma::mma_sync(acc[ct], al, bh, acc[ct]);
        }
    }
    #pragma unroll
    for (int ct=0; ct<4; ct++)
        wmma::store_matrix_sync(Cout + rt*16*132 + cg*64 + ct*16, acc[ct], 132, wmma::mem_row_major);
}

// ---------------- generic [M,128]@[128,128] split-bf16 GEMM ----------------
#define GEMM_SMEM (4*128*136*2)   // 139264 B
__global__ __launch_bounds__(256) void gemm128_kernel(
    const bf16* __restrict__ Ah, const bf16* __restrict__ Al,
    const bf16* __restrict__ Wh, const bf16* __restrict__ Wl,
    float* __restrict__ C, const float* __restrict__ bias, int M)
{
    extern __shared__ char sm[];
    bf16* sAh = (bf16*)sm;
    bf16* sAl = sAh + 128*136;
    bf16* sWh = sAl + 128*136;
    bf16* sWl = sWh + 128*136;
    float* sC = (float*)sm;   // reused after compute (67584 <= 69632)

    const int tid = threadIdx.x;
    const int m0  = blockIdx.x*128;

    for (int i = tid; i < 128*16; i += 256) {
        int r = i>>4, c8 = (i&15)*8;
        uint4 vh = make_uint4(0,0,0,0), vl = make_uint4(0,0,0,0);
        if (m0 + r < M) {
            vh = *(const uint4*)(Ah + (size_t)(m0+r)*128 + c8);
            vl = *(const uint4*)(Al + (size_t)(m0+r)*128 + c8);
        }
        *(uint4*)(sAh + r*136 + c8) = vh;
        *(uint4*)(sAl + r*136 + c8) = vl;
        *(uint4*)(sWh + r*136 + c8) = *(const uint4*)(Wh + r*128 + c8);
        *(uint4*)(sWl + r*136 + c8) = *(const uint4*)(Wl + r*128 + c8);
    }
    __syncthreads();

    const int w  = tid>>5;
    const int wr = w>>1;    // 0..3 -> 32 rows
    const int wc = w&1;     // 0..1 -> 64 cols
    wmma::fragment<wmma::accumulator,16,16,16,float> acc[2][4];
    #pragma unroll
    for (int i=0;i<2;i++)
        #pragma unroll
        for (int j=0;j<4;j++) wmma::fill_fragment(acc[i][j], 0.f);

    #pragma unroll
    for (int kk=0; kk<8; kk++) {
        wmma::fragment<wmma::matrix_a,16,16,16,bf16,wmma::row_major> ah[2], al[2];
        #pragma unroll
        for (int rt=0; rt<2; rt++) {
            wmma::load_matrix_sync(ah[rt], sAh + (wr*32+rt*16)*136 + kk*16, 136);
            wmma::load_matrix_sync(al[rt], sAl + (wr*32+rt*16)*136 + kk*16, 136);
        }
        #pragma unroll
        for (int ct=0; ct<4; ct++) {
            wmma::fragment<wmma::matrix_b,16,16,16,bf16,wmma::row_major> bh, bl;
            wmma::load_matrix_sync(bh, sWh + kk*16*136 + wc*64 + ct*16, 136);
            wmma::load_matrix_sync(bl, sWl + kk*16*136 + wc*64 + ct*16, 136);
            #pragma unroll
            for (int rt=0; rt<2; rt++) {
                wmma::mma_sync(acc[rt][ct], ah[rt], bh, acc[rt][ct]);
                wmma::mma_sync(acc[rt][ct], ah[rt], bl, acc[rt][ct]);
                wmma::mma_sync(acc[rt][ct], al[rt], bh, acc[rt][ct]);
            }
        }
    }
    __syncthreads();   // A smem reads done -> reuse as fp32 staging
    #pragma unroll
    for (int rt=0; rt<2; rt++)
        #pragma unroll
        for (int ct=0; ct<4; ct++)
            wmma::store_matrix_sync(sC + (wr*32+rt*16)*132 + wc*64 + ct*16, acc[rt][ct], 132, wmma::mem_row_major);
    __syncthreads();

    for (int i = tid; i < 128*32; i += 256) {
        int r = i>>5, c4 = (i&31)*4;
        if (m0 + r < M) {
            float4 v = *(const float4*)(sC + r*132 + c4);
            if (bias) { v.x += bias[c4]; v.y += bias[c4+1]; v.z += bias[c4+2]; v.w += bias[c4+3]; }
            *(float4*)(C + (size_t)(m0+r)*128 + c4) = v;
        }
    }
}

// ---------------- fused edge kernel: 8 nodes (128 edges) per block ----------------
// smem: EH/EL/WH/WL bf16[128][136] (139264) + TO f32[128][132] (67584)
//       + QS f32[8][128] + SC f32[128][8] + S2 f32[128][8] + DST int[128] + WEXP f32[64]
#define EDGE_SMEM (4*128*136*2 + 128*132*4 + 1024*4 + 1024*4 + 1024*4 + 128*4 + 64*4)  // 219904
__global__ __launch_bounds__(512) void edge_kernel(
    const float* __restrict__ edges, const int* __restrict__ eidx,
    const float* __restrict__ Wexp)
{
    extern __shared__ char sm[];
    bf16*  EH   = (bf16*)sm;
    bf16*  EL   = EH + 128*136;
    bf16*  WHs  = EL + 128*136;
    bf16*  WLs  = WHs + 128*136;
    float* TO   = (float*)(sm + 4*128*136*2);
    float* QS   = TO + 128*132;
    float* SC   = QS + 1024;
    float* S2   = SC + 1024;
    int*   DSTS = (int*)(S2 + 1024);
    float* WEXP = (float*)(DSTS + 128);

    const int tid   = threadIdx.x;
    const int node0 = blockIdx.x*8;
    const int e0    = node0*16;

    if (tid < 128) DSTS[tid] = eidx[NE + e0 + tid];
    if (tid >= 128 && tid < 192) WEXP[tid-128] = Wexp[tid-128];

    // Q rows for this block's 8 source nodes
    for (int i = tid; i < 1024; i += 512)
        QS[i] = g_Q[(size_t)(node0 + (i>>7))*128 + (i&127)];

    // edge tile: load fp32 once, split to bf16 hi/lo in smem
    for (int i = tid; i < 4096; i += 512) {
        int r = i>>5, c4 = (i&31)*4;
        float4 v = *(const float4*)(edges + (size_t)(e0+r)*128 + c4);
        bf16 h;
        h = __float2bfloat16(v.x); EH[r*136+c4+0]=h; EL[r*136+c4+0]=__float2bfloat16(v.x-__bfloat162float(h));
        h = __float2bfloat16(v.y); EH[r*136+c4+1]=h; EL[r*136+c4+1]=__float2bfloat16(v.y-__bfloat162float(h));
        h = __float2bfloat16(v.z); EH[r*136+c4+2]=h; EL[r*136+c4+2]=__float2bfloat16(v.z-__bfloat162float(h));
        h = __float2bfloat16(v.w); EH[r*136+c4+3]=h; EL[r*136+c4+3]=__float2bfloat16(v.w-__bfloat162float(h));
    }
    // phase-1 weights: Wek*SCALE (slot 3)
    {
        const bf16* Wh = g_w_hi + 3*16384;
        const bf16* Wl = g_w_lo + 3*16384;
        for (int i = tid; i < 2048; i += 512) {
            int r = i>>4, c8 = (i&15)*8;
            *(uint4*)(WHs + r*136 + c8) = *(const uint4*)(Wh + r*128 + c8);
            *(uint4*)(WLs + r*136 + c8) = *(const uint4*)(Wl + r*128 + c8);
        }
    }
    __syncthreads();

    mma_128x128(EH, EL, WHs, WLs, TO, tid>>5);   // TO = EK (scaled)
    __syncthreads();

    // scores[e][h] = sum_hd Q[src][h,hd] * (KS[dst][h,hd] + EK[e][h,hd])
    {
        const int w = tid>>5, lane = tid&31;
        #pragma unroll
        for (int ee = 0; ee < 8; ee++) {
            int e   = w*8 + ee;
            int nd  = e>>4;
            int dst = DSTS[e];
            float4 ks = *(const float4*)(g_KS + (size_t)dst*128 + lane*4);
            float4 q  = *(const float4*)(QS + nd*128 + lane*4);
            float4 ek = *(const float4*)(TO + e*132 + lane*4);
            float s = q.x*(ks.x+ek.x) + q.y*(ks.y+ek.y) + q.z*(ks.z+ek.z) + q.w*(ks.w+ek.w);
            s += __shfl_xor_sync(0xffffffffu, s, 1);
            s += __shfl_xor_sync(0xffffffffu, s, 2);
            if ((lane&3)==0) SC[e*8 + (lane>>2)] = s;   // head = lane/4
        }
    }
    __syncthreads();

    // load phase-2 weights (Wev, slot 4) + head expansion S2 = SC @ Wexp
    {
        const bf16* Wh = g_w_hi + 4*16384;
        const bf16* Wl = g_w_lo + 4*16384;
        for (int i = tid; i < 2048; i += 512) {
            int r = i>>4, c8 = (i&15)*8;
            *(uint4*)(WHs + r*136 + c8) = *(const uint4*)(Wh + r*128 + c8);
            *(uint4*)(WLs + r*136 + c8) = *(const uint4*)(Wl + r*128 + c8);
        }
        for (int idx = tid; idx < 1024; idx += 512) {
            int e = idx>>3, he = idx&7;
            float s = 0.f;
            #pragma unroll
            for (int h=0; h<8; h++) s += SC[e*8+h]*WEXP[h*8+he];
            S2[idx] = s;
        }
    }
    __syncthreads();

    mma_128x128(EH, EL, WHs, WLs, TO, tid>>5);   // TO = EV
    __syncthreads();

    // segment softmax over each node's 16 contiguous edges (in-place in S2)
    if (tid < 64) {
        int nd = tid>>3, he = tid&7;
        int base = nd*16;
        float m = -1e30f;
        #pragma unroll
        for (int j=0;j<16;j++) m = fmaxf(m, S2[(base+j)*8+he]);
        float ex[16]; float sum = 0.f;
        #pragma unroll
        for (int j=0;j<16;j++){ ex[j] = expf(S2[(base+j)*8+he]-m); sum += ex[j]; }
        float inv = 1.f/sum;
        #pragma unroll
        for (int j=0;j<16;j++) S2[(base+j)*8+he] = ex[j]*inv;
    }
    __syncthreads();

    // agg[node][c] = sum_j a[e][c/16] * (V[dst][c] + EV[e][c]); store bf16 hi/lo
    for (int idx = tid; idx < 1024; idx += 512) {
        int nd = idx>>7, c = idx&127, he = c>>4;
        int base = nd*16;
        float acc = 0.f;
        #pragma unroll
        for (int j=0;j<16;j++) {
            int e = base + j;
            acc += S2[e*8+he] * (g_V[(size_t)DSTS[e]*128 + c] + TO[e*132 + c]);
        }
        size_t o = (size_t)(node0 + nd)*128 + c;
        bf16 h = __float2bfloat16(acc);
        g_agg_hi[o] = h;
        g_agg_lo[o] = __float2bfloat16(acc - __bfloat162float(h));
    }
}

// ---------------- launch ----------------
extern "C" void kernel_launch(void* const* d_in, const int* in_sizes, int n_in,
                              void* d_out, int out_size)
{
    const float* x    = (const float*)d_in[0];
    const float* edges= (const float*)d_in[1];
    const int*   eidx = (const int*)  d_in[2];
    const float* Wq   = (const float*)d_in[3];
    const float* Wk   = (const float*)d_in[4];
    const float* Wv   = (const float*)d_in[5];
    const float* Wek  = (const float*)d_in[6];
    const float* Wev  = (const float*)d_in[7];
    const float* Wexp = (const float*)d_in[8];
    const float* Wout = (const float*)d_in[9];
    const float* bout = (const float*)d_in[10];
    float* out = (float*)d_out;

    bf16 *x_hi, *x_lo, *w_hi, *w_lo, *agg_hi, *agg_lo;
    float *Qg, *KSg, *Vg;
    cudaGetSymbolAddress((void**)&x_hi,  g_x_hi);
    cudaGetSymbolAddress((void**)&x_lo,  g_x_lo);
    cudaGetSymbolAddress((void**)&w_hi,  g_w_hi);
    cudaGetSymbolAddress((void**)&w_lo,  g_w_lo);
    cudaGetSymbolAddress((void**)&agg_hi,g_agg_hi);
    cudaGetSymbolAddress((void**)&agg_lo,g_agg_lo);
    cudaGetSymbolAddress((void**)&Qg,    g_Q);
    cudaGetSymbolAddress((void**)&KSg,   g_KS);
    cudaGetSymbolAddress((void**)&Vg,    g_V);

    cudaFuncSetAttribute(gemm128_kernel, cudaFuncAttributeMaxDynamicSharedMemorySize, GEMM_SMEM);
    cudaFuncSetAttribute(edge_kernel,    cudaFuncAttributeMaxDynamicSharedMemorySize, EDGE_SMEM);

    // splits: x and the six weight matrices (fold SCALE into Wk/Wek, negate Wout)
    split_kernel<<<(NN*DIMC+255)/256,256>>>(x,    x_hi,         x_lo,         1.f,     NN*DIMC);
    split_kernel<<<64,256>>>(Wq,   w_hi+0*16384, w_lo+0*16384,  1.f,     16384);
    split_kernel<<<64,256>>>(Wk,   w_hi+1*16384, w_lo+1*16384,  SCALEC,  16384);
    split_kernel<<<64,256>>>(Wv,   w_hi+2*16384, w_lo+2*16384,  1.f,     16384);
    split_kernel<<<64,256>>>(Wek,  w_hi+3*16384, w_lo+3*16384,  SCALEC,  16384);
    split_kernel<<<64,256>>>(Wev,  w_hi+4*16384, w_lo+4*16384,  1.f,     16384);
    split_kernel<<<64,256>>>(Wout, w_hi+5*16384, w_lo+5*16384, -1.f,     16384);

    const int gblocks = (NN + 127)/128;   // 157
    gemm128_kernel<<<gblocks,256,GEMM_SMEM>>>(x_hi, x_lo, w_hi+0*16384, w_lo+0*16384, Qg,  nullptr, NN);
    gemm128_kernel<<<gblocks,256,GEMM_SMEM>>>(x_hi, x_lo, w_hi+1*16384, w_lo+1*16384, KSg, nullptr, NN);
    gemm128_kernel<<<gblocks,256,GEMM_SMEM>>>(x_hi, x_lo, w_hi+2*16384, w_lo+2*16384, Vg,  nullptr, NN);

    edge_kernel<<<NN/8,512,EDGE_SMEM>>>(edges, eidx, Wexp);

    gemm128_kernel<<<gblocks,256,GEMM_SMEM>>>(agg_hi, agg_lo, w_hi+5*16384, w_lo+5*16384, out, bout, NN);
}

// round 4
// speedup vs baseline: 1.0420x; 1.0420x over previous
#include <cuda_runtime.h>
#include <cuda_bf16.h>
#include <mma.h>
#include <cstdint>

using namespace nvcuda;
typedef __nv_bfloat16 bf16;

#define NN   20000
#define DEGC 16
#define NE   (NN*DEGC)     // 320000
#define DIMC 128
#define SCALEC 0.25f       // HD^-0.5, HD=16
#define NTILES 5000        // 64 edges (4 nodes) per tile

// ---------------- scratch (__device__ globals; no allocation allowed) ----------------
__device__ float g_Q  [NN*DIMC];
__device__ float g_KS [NN*DIMC];
__device__ float g_V  [NN*DIMC];
__device__ float g_agg[NN*DIMC];
// weight slots hi/lo, plain row-major [k][n]:
// 0=Wq 1=Wk*S 2=Wv 3=-Wout 4=Wek*S 5=Wev
__device__ bf16  g_w_hi[6*DIMC*DIMC];
__device__ bf16  g_w_lo[6*DIMC*DIMC];

// ---------------- weight split: 6 slots in one launch ----------------
__global__ void wsplit_kernel(const float* __restrict__ w0, const float* __restrict__ w1,
                              const float* __restrict__ w2, const float* __restrict__ w3,
                              const float* __restrict__ w4, const float* __restrict__ w5)
{
    const float* srcs[6] = {w0, w1, w2, w3, w4, w5};
    const float  scl [6] = {1.f, SCALEC, 1.f, -1.f, SCALEC, 1.f};
    int s = blockIdx.y;
    int i = blockIdx.x*256 + threadIdx.x;          // 0..16383
    float v = srcs[s][i] * scl[s];
    bf16 h = __float2bfloat16(v);
    g_w_hi[s*16384 + i] = h;
    g_w_lo[s*16384 + i] = __float2bfloat16(v - __bfloat162float(h));
}

// ---------------- fused-split [M,128]@[128,128] GEMM, B frags from global ----------------
// smem: A hi/lo bf16[128][136] = 69632 B ; fp32 C staging reuses same region
#define GEMM_SMEM (2*128*136*2)
__global__ __launch_bounds__(256) void gemm_fused(
    const float* __restrict__ A,
    const bf16* __restrict__ WhB, const bf16* __restrict__ WlB,
    float* __restrict__ C0, float* __restrict__ C1, float* __restrict__ C2,
    const float* __restrict__ bias, int M)
{
    extern __shared__ char sm[];
    bf16* sAh = (bf16*)sm;
    bf16* sAl = sAh + 128*136;
    float* sC = (float*)sm;

    const bf16* Wh = WhB + (size_t)blockIdx.y*16384;
    const bf16* Wl = WlB + (size_t)blockIdx.y*16384;
    float* C = (blockIdx.y == 0) ? C0 : ((blockIdx.y == 1) ? C1 : C2);

    const int tid = threadIdx.x;
    const int m0  = blockIdx.x*128;

    // load fp32 A tile, split to bf16 hi/lo in smem
    for (int i = tid; i < 4096; i += 256) {
        int r = i>>5, c4 = (i&31)*4;
        float4 v = make_float4(0.f,0.f,0.f,0.f);
        if (m0 + r < M) v = *(const float4*)(A + (size_t)(m0+r)*128 + c4);
        bf16 h0=__float2bfloat16(v.x), h1=__float2bfloat16(v.y);
        bf16 h2=__float2bfloat16(v.z), h3=__float2bfloat16(v.w);
        __nv_bfloat162 hh0; hh0.x=h0; hh0.y=h1;
        __nv_bfloat162 hh1; hh1.x=h2; hh1.y=h3;
        *(__nv_bfloat162*)(sAh + r*136 + c4)     = hh0;
        *(__nv_bfloat162*)(sAh + r*136 + c4 + 2) = hh1;
        __nv_bfloat162 ll0, ll1;
        ll0.x=__float2bfloat16(v.x-__bfloat162float(h0));
        ll0.y=__float2bfloat16(v.y-__bfloat162float(h1));
        ll1.x=__float2bfloat16(v.z-__bfloat162float(h2));
        ll1.y=__float2bfloat16(v.w-__bfloat162float(h3));
        *(__nv_bfloat162*)(sAl + r*136 + c4)     = ll0;
        *(__nv_bfloat162*)(sAl + r*136 + c4 + 2) = ll1;
    }
    __syncthreads();

    const int w  = tid>>5;
    const int wr = w>>1;    // 0..3 -> 32 rows
    const int wc = w&1;     // 0..1 -> 64 cols
    wmma::fragment<wmma::accumulator,16,16,16,float> acc[2][4];
    #pragma unroll
    for (int i=0;i<2;i++)
        #pragma unroll
        for (int j=0;j<4;j++) wmma::fill_fragment(acc[i][j], 0.f);

    #pragma unroll
    for (int kk=0; kk<8; kk++) {
        wmma::fragment<wmma::matrix_a,16,16,16,bf16,wmma::row_major> ah[2], al[2];
        #pragma unroll
        for (int rt=0; rt<2; rt++) {
            wmma::load_matrix_sync(ah[rt], sAh + (wr*32+rt*16)*136 + kk*16, 136);
            wmma::load_matrix_sync(al[rt], sAl + (wr*32+rt*16)*136 + kk*16, 136);
        }
        #pragma unroll
        for (int ct=0; ct<4; ct++) {
            wmma::fragment<wmma::matrix_b,16,16,16,bf16,wmma::row_major> bh, bl;
            wmma::load_matrix_sync(bh, Wh + kk*16*128 + wc*64 + ct*16, 128);  // global (L2-hot)
            wmma::load_matrix_sync(bl, Wl + kk*16*128 + wc*64 + ct*16, 128);
            #pragma unroll
            for (int rt=0; rt<2; rt++) {
                wmma::mma_sync(acc[rt][ct], ah[rt], bh, acc[rt][ct]);
                wmma::mma_sync(acc[rt][ct], ah[rt], bl, acc[rt][ct]);
                wmma::mma_sync(acc[rt][ct], al[rt], bh, acc[rt][ct]);
            }
        }
    }
    __syncthreads();   // all A reads done -> reuse smem for fp32 C
    #pragma unroll
    for (int rt=0; rt<2; rt++)
        #pragma unroll
        for (int ct=0; ct<4; ct++)
            wmma::store_matrix_sync(sC + (wr*32+rt*16)*132 + wc*64 + ct*16, acc[rt][ct], 132, wmma::mem_row_major);
    __syncthreads();

    for (int i = tid; i < 4096; i += 256) {
        int r = i>>5, c4 = (i&31)*4;
        if (m0 + r < M) {
            float4 v = *(const float4*)(sC + r*132 + c4);
            if (bias) { v.x += bias[c4]; v.y += bias[c4+1]; v.z += bias[c4+2]; v.w += bias[c4+3]; }
            *(float4*)(C + (size_t)(m0+r)*128 + c4) = v;
        }
    }
}

// ---------------- persistent edge kernel ----------------
// smem layout (bytes):
#define EOFF_WEKH 0         // 128*136*2 = 34816
#define EOFF_WEKL 34816
#define EOFF_WEVH 69632
#define EOFF_WEVL 104448
#define EOFF_AH   139264    // 64*136*2 = 17408
#define EOFF_AL   156672
#define EOFF_C    174080    // 64*132*4 = 33792
#define EOFF_QS   207872    // 4*128*4  = 2048
#define EOFF_SE   209920    // 64*8*4   = 2048
#define EOFF_SA   211968    // 64*8*4   = 2048
#define EOFF_DST  214016    // 64*4
#define EOFF_WEXP 214272    // 64*4
#define EDGE_SMEM 214528

// 64x128 @ 128x128 split-bf16 wmma, A stride 136, W stride 136, C stride 132
__device__ __forceinline__ void mma64x128(const bf16* AH, const bf16* AL,
                                          const bf16* WH, const bf16* WL,
                                          float* C, int w)
{
    const int rt = w>>1;   // 0..3 : 16-row tile
    const int cg = w&1;    // 0..1 : 64-col group
    wmma::fragment<wmma::accumulator,16,16,16,float> acc[4];
    #pragma unroll
    for (int j=0;j<4;j++) wmma::fill_fragment(acc[j], 0.f);
    #pragma unroll
    for (int kk=0; kk<8; kk++) {
        wmma::fragment<wmma::matrix_a,16,16,16,bf16,wmma::row_major> ah, al;
        wmma::load_matrix_sync(ah, AH + rt*16*136 + kk*16, 136);
        wmma::load_matrix_sync(al, AL + rt*16*136 + kk*16, 136);
        #pragma unroll
        for (int ct=0; ct<4; ct++) {
            wmma::fragment<wmma::matrix_b,16,16,16,bf16,wmma::row_major> bh, bl;
            wmma::load_matrix_sync(bh, WH + kk*16*136 + cg*64 + ct*16, 136);
            wmma::load_matrix_sync(bl, WL + kk*16*136 + cg*64 + ct*16, 136);
            wmma::mma_sync(acc[ct], ah, bh, acc[ct]);
            wmma::mma_sync(acc[ct], ah, bl, acc[ct]);
            wmma::mma_sync(acc[ct], al, bh, acc[ct]);
        }
    }
    #pragma unroll
    for (int ct=0; ct<4; ct++)
        wmma::store_matrix_sync(C + rt*16*132 + cg*64 + ct*16, acc[ct], 132, wmma::mem_row_major);
}

// split prefetched fp32 regs -> bf16 hi/lo A smem
__device__ __forceinline__ void writeA(bf16* AH, bf16* AL, const float4* pf, int tid)
{
    #pragma unroll
    for (int i = 0; i < 8; i++) {
        int idx = tid + i*256;
        int r = idx>>5, c4 = (idx&31)*4;
        float4 v = pf[i];
        bf16 h0=__float2bfloat16(v.x), h1=__float2bfloat16(v.y);
        bf16 h2=__float2bfloat16(v.z), h3=__float2bfloat16(v.w);
        __nv_bfloat162 hh0; hh0.x=h0; hh0.y=h1;
        __nv_bfloat162 hh1; hh1.x=h2; hh1.y=h3;
        *(__nv_bfloat162*)(AH + r*136 + c4)     = hh0;
        *(__nv_bfloat162*)(AH + r*136 + c4 + 2) = hh1;
        __nv_bfloat162 ll0, ll1;
        ll0.x=__float2bfloat16(v.x-__bfloat162float(h0));
        ll0.y=__float2bfloat16(v.y-__bfloat162float(h1));
        ll1.x=__float2bfloat16(v.z-__bfloat162float(h2));
        ll1.y=__float2bfloat16(v.w-__bfloat162float(h3));
        *(__nv_bfloat162*)(AL + r*136 + c4)     = ll0;
        *(__nv_bfloat162*)(AL + r*136 + c4 + 2) = ll1;
    }
}

__global__ __launch_bounds__(256, 1) void edge_kernel(
    const float* __restrict__ edges, const int* __restrict__ eidx,
    const float* __restrict__ Wexp)
{
    extern __shared__ char sm[];
    bf16*  WEKH = (bf16*)(sm + EOFF_WEKH);
    bf16*  WEKL = (bf16*)(sm + EOFF_WEKL);
    bf16*  WEVH = (bf16*)(sm + EOFF_WEVH);
    bf16*  WEVL = (bf16*)(sm + EOFF_WEVL);
    bf16*  AH   = (bf16*)(sm + EOFF_AH);
    bf16*  AL   = (bf16*)(sm + EOFF_AL);
    float* C    = (float*)(sm + EOFF_C);
    float* QS   = (float*)(sm + EOFF_QS);
    float* SE   = (float*)(sm + EOFF_SE);
    float* SA   = (float*)(sm + EOFF_SA);
    int*   DST  = (int*)  (sm + EOFF_DST);
    float* WEXP = (float*)(sm + EOFF_WEXP);

    const int tid = threadIdx.x;
    const int w   = tid >> 5;

    // ---- prologue: resident weights (Wek=slot4, Wev=slot5), Wexp ----
    for (int i = tid; i < 2048; i += 256) {
        int r = i>>4, c8 = (i&15)*8;
        *(uint4*)(WEKH + r*136 + c8) = *(const uint4*)(g_w_hi + 4*16384 + r*128 + c8);
        *(uint4*)(WEKL + r*136 + c8) = *(const uint4*)(g_w_lo + 4*16384 + r*128 + c8);
        *(uint4*)(WEVH + r*136 + c8) = *(const uint4*)(g_w_hi + 5*16384 + r*128 + c8);
        *(uint4*)(WEVL + r*136 + c8) = *(const uint4*)(g_w_lo + 5*16384 + r*128 + c8);
    }
    if (tid < 64) WEXP[tid] = Wexp[tid];

    // prefetch + write A for first tile
    int t = blockIdx.x;
    float4 pf[8];
    #pragma unroll
    for (int i = 0; i < 8; i++) {
        int idx = tid + i*256;
        int r = idx>>5, c4 = (idx&31)*4;
        pf[i] = *(const float4*)(edges + (size_t)(t*64 + r)*128 + c4);
    }
    writeA(AH, AL, pf, tid);
    __syncthreads();

    for (; t < NTILES; t += gridDim.x) {
        const int node0 = t*4;
        const int e0    = t*64;
        const int tn    = t + gridDim.x;

        // per-tile loads: dst indices + Q rows; issue next-tile edge prefetch
        if (tid < 64) DST[tid] = eidx[NE + e0 + tid];
        for (int i = tid; i < 512; i += 256)
            QS[i] = g_Q[(size_t)(node0 + (i>>7))*128 + (i&127)];
        #pragma unroll
        for (int i = 0; i < 8; i++) {
            int idx = tid + i*256;
            int r = idx>>5, c4 = (idx&31)*4;
            pf[i] = (tn < NTILES)
                  ? *(const float4*)(edges + (size_t)(tn*64 + r)*128 + c4)
                  : make_float4(0.f,0.f,0.f,0.f);
        }

        // EK = A @ Wek  (scaled) -> C
        mma64x128(AH, AL, WEKH, WEKL, C, w);
        __syncthreads();

        // scores: 4 threads per edge, each owns 2 heads completely
        {
            const int e = tid>>2, q = tid&3;
            const int nd = e>>4;
            const int dst = DST[e];
            const float* ks = g_KS + (size_t)dst*128 + q*32;
            const float* qv = QS + nd*128 + q*32;
            const float* ek = C + e*132 + q*32;
            float s0 = 0.f, s1 = 0.f;
            #pragma unroll
            for (int j = 0; j < 16; j += 4) {
                float4 k4 = *(const float4*)(ks + j);
                float4 q4 = *(const float4*)(qv + j);
                float4 e4 = *(const float4*)(ek + j);
                s0 += q4.x*(k4.x+e4.x) + q4.y*(k4.y+e4.y) + q4.z*(k4.z+e4.z) + q4.w*(k4.w+e4.w);
            }
            #pragma unroll
            for (int j = 16; j < 32; j += 4) {
                float4 k4 = *(const float4*)(ks + j);
                float4 q4 = *(const float4*)(qv + j);
                float4 e4 = *(const float4*)(ek + j);
                s1 += q4.x*(k4.x+e4.x) + q4.y*(k4.y+e4.y) + q4.z*(k4.z+e4.z) + q4.w*(k4.w+e4.w);
            }
            SE[e*8 + 2*q]     = s0;
            SE[e*8 + 2*q + 1] = s1;
        }
        __syncthreads();

        // EV = A @ Wev -> C (C free after score phase)
        mma64x128(AH, AL, WEVH, WEVL, C, w);
        __syncthreads();

        // head expansion: se = s @ Wexp  (512 outputs)
        for (int idx = tid; idx < 512; idx += 256) {
            int e = idx>>3, he = idx&7;
            float v = 0.f;
            #pragma unroll
            for (int h = 0; h < 8; h++) v += SE[e*8+h]*WEXP[h*8+he];
            SA[idx] = v;
        }
        __syncthreads();

        // segment softmax (32 threads) + stage next A (all threads)
        if (tid < 32) {
            int nd = tid>>3, he = tid&7;
            int base = nd*16;
            float m = -1e30f;
            #pragma unroll
            for (int j=0;j<16;j++) m = fmaxf(m, SA[(base+j)*8+he]);
            float ex[16]; float su = 0.f;
            #pragma unroll
            for (int j=0;j<16;j++){ ex[j] = __expf(SA[(base+j)*8+he]-m); su += ex[j]; }
            float inv = 1.f/su;
            #pragma unroll
            for (int j=0;j<16;j++) SA[(base+j)*8+he] = ex[j]*inv;
        }
        writeA(AH, AL, pf, tid);   // A free after EV mma
        __syncthreads();

        // aggregation: thread -> (node, col) and (node, col+64)
        {
            const int nd = tid>>6, c = tid&63;
            const int base = nd*16;
            const int he0 = c>>4, he1 = (c+64)>>4;
            float a0 = 0.f, a1 = 0.f;
            #pragma unroll
            for (int j = 0; j < 16; j++) {
                const int e = base + j;
                const float* vr = g_V + (size_t)DST[e]*128;
                a0 += SA[e*8+he0]*(vr[c]    + C[e*132+c]);
                a1 += SA[e*8+he1]*(vr[c+64] + C[e*132+c+64]);
            }
            size_t o = (size_t)(node0+nd)*128;
            g_agg[o+c]    = a0;
            g_agg[o+c+64] = a1;
        }
        __syncthreads();
    }
}

// ---------------- launch ----------------
extern "C" void kernel_launch(void* const* d_in, const int* in_sizes, int n_in,
                              void* d_out, int out_size)
{
    const float* x    = (const float*)d_in[0];
    const float* edges= (const float*)d_in[1];
    const int*   eidx = (const int*)  d_in[2];
    const float* Wq   = (const float*)d_in[3];
    const float* Wk   = (const float*)d_in[4];
    const float* Wv   = (const float*)d_in[5];
    const float* Wek  = (const float*)d_in[6];
    const float* Wev  = (const float*)d_in[7];
    const float* Wexp = (const float*)d_in[8];
    const float* Wout = (const float*)d_in[9];
    const float* bout = (const float*)d_in[10];
    float* out = (float*)d_out;

    bf16 *w_hi, *w_lo;
    float *Qg, *KSg, *Vg, *aggg;
    cudaGetSymbolAddress((void**)&w_hi, g_w_hi);
    cudaGetSymbolAddress((void**)&w_lo, g_w_lo);
    cudaGetSymbolAddress((void**)&Qg,   g_Q);
    cudaGetSymbolAddress((void**)&KSg,  g_KS);
    cudaGetSymbolAddress((void**)&Vg,   g_V);
    cudaGetSymbolAddress((void**)&aggg, g_agg);

    cudaFuncSetAttribute(gemm_fused,  cudaFuncAttributeMaxDynamicSharedMemorySize, GEMM_SMEM);
    cudaFuncSetAttribute(edge_kernel, cudaFuncAttributeMaxDynamicSharedMemorySize, EDGE_SMEM);

    // weights: 0=Wq 1=Wk*S 2=Wv 3=-Wout 4=Wek*S 5=Wev
    wsplit_kernel<<<dim3(64,6),256>>>(Wq, Wk, Wv, Wout, Wek, Wev);

    // Q / KS / V in one launch (x split in-kernel)
    gemm_fused<<<dim3((NN+127)/128,3),256,GEMM_SMEM>>>(x, w_hi, w_lo, Qg, KSg, Vg, nullptr, NN);

    // persistent fused edge kernel
    edge_kernel<<<148,256,EDGE_SMEM>>>(edges, eidx, Wexp);

    // out = agg @ (-Wout) + bout
    gemm_fused<<<dim3((NN+127)/128,1),256,GEMM_SMEM>>>(aggg, w_hi+3*16384, w_lo+3*16384,
                                                       out, out, out, bout, NN);
}

// round 5
// speedup vs baseline: 1.0743x; 1.0310x over previous
#include <cuda_runtime.h>
#include <cuda_bf16.h>
#include <mma.h>
#include <cstdint>

using namespace nvcuda;
typedef __nv_bfloat16 bf16;

#define NN   20000
#define DEGC 16
#define NE   (NN*DEGC)     // 320000
#define DIMC 128
#define SCALEC 0.25f       // HD^-0.5, HD=16
#define NTILES 5000        // 64 edges (4 nodes) per tile

#define BAR_SYNC(id,cnt)   asm volatile("bar.sync %0, %1;"   :: "r"(id), "r"(cnt) : "memory")
#define BAR_ARRIVE(id,cnt) asm volatile("bar.arrive %0, %1;" :: "r"(id), "r"(cnt) : "memory")

// ---------------- scratch (__device__ globals; no allocation allowed) ----------------
__device__ float g_Q  [NN*DIMC];
__device__ float g_KS [NN*DIMC];
__device__ float g_V  [NN*DIMC];
__device__ float g_agg[NN*DIMC];
// weight slots hi/lo, plain row-major [k][n]:
// 0=Wq 1=Wk*S 2=Wv 3=-Wout 4=Wek*S 5=Wev
__device__ bf16  g_w_hi[6*DIMC*DIMC];
__device__ bf16  g_w_lo[6*DIMC*DIMC];

// ---------------- weight split: 6 slots in one launch ----------------
__global__ void wsplit_kernel(const float* __restrict__ w0, const float* __restrict__ w1,
                              const float* __restrict__ w2, const float* __restrict__ w3,
                              const float* __restrict__ w4, const float* __restrict__ w5)
{
    const float* srcs[6] = {w0, w1, w2, w3, w4, w5};
    const float  scl [6] = {1.f, SCALEC, 1.f, -1.f, SCALEC, 1.f};
    int s = blockIdx.y;
    int i = blockIdx.x*256 + threadIdx.x;
    float v = srcs[s][i] * scl[s];
    bf16 h = __float2bfloat16(v);
    g_w_hi[s*16384 + i] = h;
    g_w_lo[s*16384 + i] = __float2bfloat16(v - __bfloat162float(h));
}

// ---------------- multi-slot [M,128]@[128,128] split-bf16 GEMM ----------------
// smem: A hi/lo bf16[128][136] (69632) + W hi/lo bf16[128][136] (69632); C overlays W
#define GEMM_SMEM (4*128*136*2)
__global__ __launch_bounds__(512) void gemm_multi(
    const float* __restrict__ A, int slot0, int nslots,
    float* __restrict__ O0, float* __restrict__ O1, float* __restrict__ O2,
    const float* __restrict__ bias, int M)
{
    extern __shared__ char sm[];
    bf16* sAh = (bf16*)sm;
    bf16* sAl = sAh + 128*136;
    bf16* sWh = sAl + 128*136;
    bf16* sWl = sWh + 128*136;
    float* sC = (float*)(sm + 2*128*136*2);  // overlays sWh/sWl (67584 <= 69632)

    const int tid = threadIdx.x;
    const int m0  = blockIdx.x*128;

    // load fp32 A tile, split to bf16 hi/lo
    for (int i = tid; i < 4096; i += 512) {
        int r = i>>5, c4 = (i&31)*4;
        float4 v = make_float4(0.f,0.f,0.f,0.f);
        if (m0 + r < M) v = *(const float4*)(A + (size_t)(m0+r)*128 + c4);
        bf16 h0=__float2bfloat16(v.x), h1=__float2bfloat16(v.y);
        bf16 h2=__float2bfloat16(v.z), h3=__float2bfloat16(v.w);
        __nv_bfloat162 hh0; hh0.x=h0; hh0.y=h1;
        __nv_bfloat162 hh1; hh1.x=h2; hh1.y=h3;
        *(__nv_bfloat162*)(sAh + r*136 + c4)     = hh0;
        *(__nv_bfloat162*)(sAh + r*136 + c4 + 2) = hh1;
        __nv_bfloat162 ll0, ll1;
        ll0.x=__float2bfloat16(v.x-__bfloat162float(h0));
        ll0.y=__float2bfloat16(v.y-__bfloat162float(h1));
        ll1.x=__float2bfloat16(v.z-__bfloat162float(h2));
        ll1.y=__float2bfloat16(v.w-__bfloat162float(h3));
        *(__nv_bfloat162*)(sAl + r*136 + c4)     = ll0;
        *(__nv_bfloat162*)(sAl + r*136 + c4 + 2) = ll1;
    }

    const int w  = tid>>5;        // 0..15
    const int wr = w>>2;          // 0..3 -> 32 rows
    const int wc = w&3;           // 0..3 -> 32 cols

    for (int s = 0; s < nslots; s++) {
        const bf16* Wh = g_w_hi + (size_t)(slot0+s)*16384;
        const bf16* Wl = g_w_lo + (size_t)(slot0+s)*16384;
        for (int i = tid; i < 1024; i += 512) {
            int r = i>>3, c16 = (i&7)*16;
            *(uint4*)(sWh + r*136 + c16)     = *(const uint4*)(Wh + r*128 + c16);
            *(uint4*)(sWh + r*136 + c16 + 8) = *(const uint4*)(Wh + r*128 + c16 + 8);
            *(uint4*)(sWl + r*136 + c16)     = *(const uint4*)(Wl + r*128 + c16);
            *(uint4*)(sWl + r*136 + c16 + 8) = *(const uint4*)(Wl + r*128 + c16 + 8);
        }
        __syncthreads();

        wmma::fragment<wmma::accumulator,16,16,16,float> acc[2][2];
        #pragma unroll
        for (int i=0;i<2;i++)
            #pragma unroll
            for (int j=0;j<2;j++) wmma::fill_fragment(acc[i][j], 0.f);

        #pragma unroll
        for (int kk=0; kk<8; kk++) {
            wmma::fragment<wmma::matrix_a,16,16,16,bf16,wmma::row_major> ah[2], al[2];
            #pragma unroll
            for (int mt=0; mt<2; mt++) {
                wmma::load_matrix_sync(ah[mt], sAh + (wr*32+mt*16)*136 + kk*16, 136);
                wmma::load_matrix_sync(al[mt], sAl + (wr*32+mt*16)*136 + kk*16, 136);
            }
            #pragma unroll
            for (int nt=0; nt<2; nt++) {
                wmma::fragment<wmma::matrix_b,16,16,16,bf16,wmma::row_major> bh, bl;
                wmma::load_matrix_sync(bh, sWh + kk*16*136 + wc*32 + nt*16, 136);
                wmma::load_matrix_sync(bl, sWl + kk*16*136 + wc*32 + nt*16, 136);
                #pragma unroll
                for (int mt=0; mt<2; mt++) {
                    wmma::mma_sync(acc[mt][nt], ah[mt], bh, acc[mt][nt]);
                    wmma::mma_sync(acc[mt][nt], ah[mt], bl, acc[mt][nt]);
                    wmma::mma_sync(acc[mt][nt], al[mt], bh, acc[mt][nt]);
                }
            }
        }
        __syncthreads();   // W reads done -> sC overlay safe
        #pragma unroll
        for (int mt=0; mt<2; mt++)
            #pragma unroll
            for (int nt=0; nt<2; nt++)
                wmma::store_matrix_sync(sC + (wr*32+mt*16)*132 + wc*32 + nt*16, acc[mt][nt], 132, wmma::mem_row_major);
        __syncthreads();

        float* C = (s == 0) ? O0 : ((s == 1) ? O1 : O2);
        for (int i = tid; i < 4096; i += 512) {
            int r = i>>5, c4 = (i&31)*4;
            if (m0 + r < M) {
                float4 v = *(const float4*)(sC + r*132 + c4);
                if (bias) { v.x += bias[c4]; v.y += bias[c4+1]; v.z += bias[c4+2]; v.w += bias[c4+3]; }
                *(float4*)(C + (size_t)(m0+r)*128 + c4) = v;
            }
        }
        __syncthreads();   // sC reads done before next slot overwrites W region
    }
}

// ---------------- persistent warp-specialized edge kernel ----------------
#define EOFF_WEKH 0         // 128*136*2 = 34816
#define EOFF_WEKL 34816
#define EOFF_WEVH 69632
#define EOFF_WEVL 104448
#define EOFF_AH   139264    // 64*136*2 = 17408
#define EOFF_AL   156672
#define EOFF_C    174080    // 64*132*4 = 33792
#define EOFF_QS   207872    // 4*128*4  = 2048
#define EOFF_SE   209920    // 64*8*4   = 2048
#define EOFF_SA   211968    // 64*8*4   = 2048
#define EOFF_DST  214016    // 64*4
#define EOFF_WEXP 214272    // 64*4
#define EDGE_SMEM 214528

// split prefetched fp32 regs -> bf16 hi/lo A smem (256 threads, ct in [0,256))
__device__ __forceinline__ void writeA(bf16* AH, bf16* AL, const float4* pf, int ct)
{
    #pragma unroll
    for (int i = 0; i < 8; i++) {
        int idx = ct + i*256;
        int r = idx>>5, c4 = (idx&31)*4;
        float4 v = pf[i];
        bf16 h0=__float2bfloat16(v.x), h1=__float2bfloat16(v.y);
        bf16 h2=__float2bfloat16(v.z), h3=__float2bfloat16(v.w);
        __nv_bfloat162 hh0; hh0.x=h0; hh0.y=h1;
        __nv_bfloat162 hh1; hh1.x=h2; hh1.y=h3;
        *(__nv_bfloat162*)(AH + r*136 + c4)     = hh0;
        *(__nv_bfloat162*)(AH + r*136 + c4 + 2) = hh1;
        __nv_bfloat162 ll0, ll1;
        ll0.x=__float2bfloat16(v.x-__bfloat162float(h0));
        ll0.y=__float2bfloat16(v.y-__bfloat162float(h1));
        ll1.x=__float2bfloat16(v.z-__bfloat162float(h2));
        ll1.y=__float2bfloat16(v.w-__bfloat162float(h3));
        *(__nv_bfloat162*)(AL + r*136 + c4)     = ll0;
        *(__nv_bfloat162*)(AL + r*136 + c4 + 2) = ll1;
    }
}

__global__ __launch_bounds__(512, 1) void edge_kernel(
    const float* __restrict__ edges, const int* __restrict__ eidx,
    const float* __restrict__ Wexp)
{
    extern __shared__ char sm[];
    bf16*  WEKH = (bf16*)(sm + EOFF_WEKH);
    bf16*  WEKL = (bf16*)(sm + EOFF_WEKL);
    bf16*  WEVH = (bf16*)(sm + EOFF_WEVH);
    bf16*  WEVL = (bf16*)(sm + EOFF_WEVL);
    bf16*  AH   = (bf16*)(sm + EOFF_AH);
    bf16*  AL   = (bf16*)(sm + EOFF_AL);
    float* C    = (float*)(sm + EOFF_C);
    float* QS   = (float*)(sm + EOFF_QS);
    float* SE   = (float*)(sm + EOFF_SE);
    float* SA   = (float*)(sm + EOFF_SA);
    int*   DST  = (int*)  (sm + EOFF_DST);
    float* WEXP = (float*)(sm + EOFF_WEXP);

    const int tid = threadIdx.x;
    const int wid = tid >> 5;

    // prologue: resident weights + Wexp (all 512 threads)
    for (int i = tid; i < 2048; i += 512) {
        int r = i>>4, c8 = (i&15)*8;
        *(uint4*)(WEKH + r*136 + c8) = *(const uint4*)(g_w_hi + 4*16384 + r*128 + c8);
        *(uint4*)(WEKL + r*136 + c8) = *(const uint4*)(g_w_lo + 4*16384 + r*128 + c8);
        *(uint4*)(WEVH + r*136 + c8) = *(const uint4*)(g_w_hi + 5*16384 + r*128 + c8);
        *(uint4*)(WEVL + r*136 + c8) = *(const uint4*)(g_w_lo + 5*16384 + r*128 + c8);
    }
    if (tid < 64) WEXP[tid] = Wexp[tid];
    __syncthreads();

    if (wid < 8) {
        // ======== producer: MMA warps ========
        const int rt = wid>>1;   // 16-row tile
        const int cg = wid&1;    // 64-col group
        for (int t = blockIdx.x; t < NTILES; t += gridDim.x) {
            BAR_SYNC(4, 512);    // A(t) staged, C free

            // EK = A @ Wek -> C
            {
                wmma::fragment<wmma::accumulator,16,16,16,float> aK[4];
                #pragma unroll
                for (int j=0;j<4;j++) wmma::fill_fragment(aK[j], 0.f);
                #pragma unroll
                for (int kk=0; kk<8; kk++) {
                    wmma::fragment<wmma::matrix_a,16,16,16,bf16,wmma::row_major> ah, al;
                    wmma::load_matrix_sync(ah, AH + rt*16*136 + kk*16, 136);
                    wmma::load_matrix_sync(al, AL + rt*16*136 + kk*16, 136);
                    #pragma unroll
                    for (int ct2=0; ct2<4; ct2++) {
                        wmma::fragment<wmma::matrix_b,16,16,16,bf16,wmma::row_major> bh, bl;
                        wmma::load_matrix_sync(bh, WEKH + kk*16*136 + cg*64 + ct2*16, 136);
                        wmma::load_matrix_sync(bl, WEKL + kk*16*136 + cg*64 + ct2*16, 136);
                        wmma::mma_sync(aK[ct2], ah, bh, aK[ct2]);
                        wmma::mma_sync(aK[ct2], ah, bl, aK[ct2]);
                        wmma::mma_sync(aK[ct2], al, bh, aK[ct2]);
                    }
                }
                #pragma unroll
                for (int ct2=0; ct2<4; ct2++)
                    wmma::store_matrix_sync(C + rt*16*132 + cg*64 + ct2*16, aK[ct2], 132, wmma::mem_row_major);
            }
            BAR_ARRIVE(1, 512);  // EK ready for consumers

            // EV = A @ Wev -> registers (overlaps score phase)
            wmma::fragment<wmma::accumulator,16,16,16,float> aV[4];
            #pragma unroll
            for (int j=0;j<4;j++) wmma::fill_fragment(aV[j], 0.f);
            #pragma unroll
            for (int kk=0; kk<8; kk++) {
                wmma::fragment<wmma::matrix_a,16,16,16,bf16,wmma::row_major> ah, al;
                wmma::load_matrix_sync(ah, AH + rt*16*136 + kk*16, 136);
                wmma::load_matrix_sync(al, AL + rt*16*136 + kk*16, 136);
                #pragma unroll
                for (int ct2=0; ct2<4; ct2++) {
                    wmma::fragment<wmma::matrix_b,16,16,16,bf16,wmma::row_major> bh, bl;
                    wmma::load_matrix_sync(bh, WEVH + kk*16*136 + cg*64 + ct2*16, 136);
                    wmma::load_matrix_sync(bl, WEVL + kk*16*136 + cg*64 + ct2*16, 136);
                    wmma::mma_sync(aV[ct2], ah, bh, aV[ct2]);
                    wmma::mma_sync(aV[ct2], ah, bl, aV[ct2]);
                    wmma::mma_sync(aV[ct2], al, bh, aV[ct2]);
                }
            }
            BAR_SYNC(2, 512);    // consumers done reading C (scores)
            #pragma unroll
            for (int ct2=0; ct2<4; ct2++)
                wmma::store_matrix_sync(C + rt*16*132 + cg*64 + ct2*16, aV[ct2], 132, wmma::mem_row_major);
            BAR_ARRIVE(3, 512);  // EV ready
        }
    } else {
        // ======== consumer: scalar warps ========
        const int ct = tid - 256;   // 0..255
        int t = blockIdx.x;
        float4 pf[8];

        // preload tile t0
        #pragma unroll
        for (int i = 0; i < 8; i++) {
            int idx = ct + i*256;
            int r = idx>>5, c4 = (idx&31)*4;
            pf[i] = *(const float4*)(edges + (size_t)(t*64 + r)*128 + c4);
        }
        writeA(AH, AL, pf, ct);
        if (ct < 64) DST[ct] = eidx[NE + t*64 + ct];
        for (int i = ct; i < 512; i += 256)
            QS[i] = g_Q[(size_t)(t*4 + (i>>7))*128 + (i&127)];
        BAR_SYNC(5, 256);        // DST/QS/A visible to all consumers
        BAR_ARRIVE(4, 512);      // release producers

        for (; t < NTILES; t += gridDim.x) {
            const int node0 = t*4;
            const int tn    = t + gridDim.x;
            const int e  = ct>>2, q = ct&3, nd = e>>4;
            const int dst = DST[e];

            // prefetch KS row quarter into regs (hides L2 latency under EK mma)
            float4 ks[8];
            #pragma unroll
            for (int j = 0; j < 8; j++)
                ks[j] = *(const float4*)(g_KS + (size_t)dst*128 + q*32 + j*4);

            BAR_SYNC(1, 512);    // EK in C

            // scores: 4 threads per edge, 2 heads each
            {
                const float* qv = QS + nd*128 + q*32;
                const float* ek = C + e*132 + q*32;
                float s0 = 0.f, s1 = 0.f;
                #pragma unroll
                for (int j = 0; j < 4; j++) {
                    float4 q4 = *(const float4*)(qv + j*4);
                    float4 e4 = *(const float4*)(ek + j*4);
                    s0 += q4.x*(ks[j].x+e4.x) + q4.y*(ks[j].y+e4.y)
                        + q4.z*(ks[j].z+e4.z) + q4.w*(ks[j].w+e4.w);
                }
                #pragma unroll
                for (int j = 4; j < 8; j++) {
                    float4 q4 = *(const float4*)(qv + j*4);
                    float4 e4 = *(const float4*)(ek + j*4);
                    s1 += q4.x*(ks[j].x+e4.x) + q4.y*(ks[j].y+e4.y)
                        + q4.z*(ks[j].z+e4.z) + q4.w*(ks[j].w+e4.w);
                }
                SE[e*8 + 2*q]     = s0;
                SE[e*8 + 2*q + 1] = s1;
            }
            BAR_ARRIVE(2, 512);  // C free -> producers store EV
            BAR_SYNC(5, 256);    // SE complete

            // head expansion
            for (int i = ct; i < 512; i += 256) {
                int ee = i>>3, he = i&7;
                float v = 0.f;
                #pragma unroll
                for (int h = 0; h < 8; h++) v += SE[ee*8+h]*WEXP[h*8+he];
                SA[i] = v;
            }
            BAR_SYNC(5, 256);    // SA complete

            // segment softmax (32 threads), others prefetch next edge tile
            if (ct < 32) {
                int nd2 = ct>>3, he = ct&7;
                int base = nd2*16;
                float m = -1e30f;
                #pragma unroll
                for (int j=0;j<16;j++) m = fmaxf(m, SA[(base+j)*8+he]);
                float ex[16]; float su = 0.f;
                #pragma unroll
                for (int j=0;j<16;j++){ ex[j] = __expf(SA[(base+j)*8+he]-m); su += ex[j]; }
                float inv = 1.f/su;
                #pragma unroll
                for (int j=0;j<16;j++) SA[(base+j)*8+he] = ex[j]*inv;
            }
            #pragma unroll
            for (int i = 0; i < 8; i++) {
                int idx = ct + i*256;
                int r = idx>>5, c4 = (idx&31)*4;
                pf[i] = (tn < NTILES)
                      ? *(const float4*)(edges + (size_t)(tn*64 + r)*128 + c4)
                      : make_float4(0.f,0.f,0.f,0.f);
            }
            BAR_SYNC(5, 256);    // softmax done
            BAR_SYNC(3, 512);    // EV in C

            // aggregation
            {
                const int nd2 = ct>>6, c = ct&63;
                const int base = nd2*16;
                const int he0 = c>>4, he1 = (c+64)>>4;
                float a0 = 0.f, a1 = 0.f;
                #pragma unroll
                for (int j = 0; j < 16; j++) {
                    const int ee = base + j;
                    const float* vr = g_V + (size_t)DST[ee]*128;
                    a0 += SA[ee*8+he0]*(vr[c]    + C[ee*132+c]);
                    a1 += SA[ee*8+he1]*(vr[c+64] + C[ee*132+c+64]);
                }
                size_t o = (size_t)(node0+nd2)*128;
                g_agg[o+c]    = a0;
                g_agg[o+c+64] = a1;
            }
            BAR_SYNC(5, 256);    // consumers done with DST/QS/SA/C

            if (tn < NTILES) {
                if (ct < 64) DST[ct] = eidx[NE + tn*64 + ct];
                for (int i = ct; i < 512; i += 256)
                    QS[i] = g_Q[(size_t)(tn*4 + (i>>7))*128 + (i&127)];
                writeA(AH, AL, pf, ct);
                BAR_SYNC(5, 256); // next-tile DST/QS visible to all consumers
            }
            BAR_ARRIVE(4, 512);  // A staged, C free
        }
    }
}

// ---------------- launch ----------------
extern "C" void kernel_launch(void* const* d_in, const int* in_sizes, int n_in,
                              void* d_out, int out_size)
{
    const float* x    = (const float*)d_in[0];
    const float* edges= (const float*)d_in[1];
    const int*   eidx = (const int*)  d_in[2];
    const float* Wq   = (const float*)d_in[3];
    const float* Wk   = (const float*)d_in[4];
    const float* Wv   = (const float*)d_in[5];
    const float* Wek  = (const float*)d_in[6];
    const float* Wev  = (const float*)d_in[7];
    const float* Wexp = (const float*)d_in[8];
    const float* Wout = (const float*)d_in[9];
    const float* bout = (const float*)d_in[10];
    float* out = (float*)d_out;

    float *Qg, *KSg, *Vg, *aggg;
    cudaGetSymbolAddress((void**)&Qg,   g_Q);
    cudaGetSymbolAddress((void**)&KSg,  g_KS);
    cudaGetSymbolAddress((void**)&Vg,   g_V);
    cudaGetSymbolAddress((void**)&aggg, g_agg);

    cudaFuncSetAttribute(gemm_multi,  cudaFuncAttributeMaxDynamicSharedMemorySize, GEMM_SMEM);
    cudaFuncSetAttribute(edge_kernel, cudaFuncAttributeMaxDynamicSharedMemorySize, EDGE_SMEM);

    // weights: 0=Wq 1=Wk*S 2=Wv 3=-Wout 4=Wek*S 5=Wev
    wsplit_kernel<<<dim3(64,6),256>>>(Wq, Wk, Wv, Wout, Wek, Wev);

    // Q / KS / V: A split once per block, 3 slots
    gemm_multi<<<(NN+127)/128,512,GEMM_SMEM>>>(x, 0, 3, Qg, KSg, Vg, nullptr, NN);

    // persistent warp-specialized fused edge kernel
    edge_kernel<<<148,512,EDGE_SMEM>>>(edges, eidx, Wexp);

    // out = agg @ (-Wout) + bout
    gemm_multi<<<(NN+127)/128,512,GEMM_SMEM>>>(aggg, 3, 1, out, out, out, bout, NN);
}

// round 6
// speedup vs baseline: 1.2015x; 1.1184x over previous
#include <cuda_runtime.h>
#include <cuda_bf16.h>
#include <mma.h>
#include <cstdint>

using namespace nvcuda;
typedef __nv_bfloat16 bf16;

#define NN   20000
#define DEGC 16
#define NE   (NN*DEGC)     // 320000
#define DIMC 128
#define SCALEC 0.25f       // HD^-0.5, HD=16
#define NT8  2500          // tiles of 8 nodes / 128 edges

// ---------------- scratch (__device__ globals; no allocation allowed) ----------------
__device__ float g_Q   [NN*DIMC];
__device__ float g_KS  [NN*DIMC];
__device__ float g_V   [NN*DIMC];
__device__ float g_P   [NN*8*DIMC];   // P[n][h][k] = sum_{d in h} Q[n,d]*Wek[k,d]*S
__device__ float g_z   [NN*8*DIMC];   // z[n][h][k] = sum_{e in n} a[e,h]*E[e,k]
__device__ float g_aggv[NN*DIMC];     // sum_e a[e,h(c)]*V[dst,c]
// weight slots hi/lo, row-major [k][n]: 0=Wq 1=Wk*S 2=Wv  (for QKV gemm)
__device__ bf16  g_w_hi[3*DIMC*DIMC];
__device__ bf16  g_w_lo[3*DIMC*DIMC];
// big output weight [1152][128]: rows 0..127 = -Wout ; rows 128+h*128+k = -Wcomb[h,k]
__device__ bf16  g_wbig_hi[1152*DIMC];
__device__ bf16  g_wbig_lo[1152*DIMC];

// ---------------- weight split: 3 slots ----------------
__global__ void wsplit_kernel(const float* __restrict__ w0, const float* __restrict__ w1,
                              const float* __restrict__ w2)
{
    const float* srcs[3] = {w0, w1, w2};
    const float  scl [3] = {1.f, SCALEC, 1.f};
    int s = blockIdx.y;
    int i = blockIdx.x*256 + threadIdx.x;
    float v = srcs[s][i] * scl[s];
    bf16 h = __float2bfloat16(v);
    g_w_hi[s*16384 + i] = h;
    g_w_lo[s*16384 + i] = __float2bfloat16(v - __bfloat162float(h));
}

// ---------------- Wbig builder: -Wout stacked with -Wev@Wout fold ----------------
__global__ void wcomb_kernel(const float* __restrict__ Wev, const float* __restrict__ Wout)
{
    int i = blockIdx.x*256 + threadIdx.x;   // 0..147455
    int j = i>>7, c = i&127;
    float v;
    if (j < 128) {
        v = -Wout[j*128 + c];
    } else {
        int hk = j - 128;
        int h = hk>>7, k = hk&127;
        float s = 0.f;
        #pragma unroll
        for (int d = 0; d < 16; d++)
            s += Wev[k*128 + h*16 + d] * Wout[(h*16 + d)*128 + c];
        v = -s;
    }
    bf16 hh = __float2bfloat16(v);
    g_wbig_hi[i] = hh;
    g_wbig_lo[i] = __float2bfloat16(v - __bfloat162float(hh));
}

// ---------------- P precompute: P[n][h][k] ----------------
// block = 16 nodes, 512 threads; WekT in smem (transposed, stride 129)
#define PK_SMEM (128*129*4 + 16*128*4)   // 66048 + 8192 = 74240
__global__ __launch_bounds__(512) void pkern(const float* __restrict__ Wek)
{
    extern __shared__ char sm[];
    float* WekT = (float*)sm;              // [d][k] stride 129
    float* Qs   = (float*)(sm + 128*129*4);

    const int tid = threadIdx.x;
    const int nb0 = blockIdx.x*16;

    for (int i = tid; i < 16384; i += 512) {
        int k = i>>7, d = i&127;
        WekT[d*129 + k] = Wek[k*128 + d] * SCALEC;
    }
    for (int i = tid; i < 2048; i += 512)
        Qs[i] = g_Q[(size_t)(nb0 + (i>>7))*128 + (i&127)];
    __syncthreads();

    const int nl = tid>>5, lane = tid&31;
    #pragma unroll
    for (int h = 0; h < 8; h++) {
        float q[16];
        #pragma unroll
        for (int d = 0; d < 16; d++) q[d] = Qs[nl*128 + h*16 + d];
        #pragma unroll
        for (int kc = 0; kc < 4; kc++) {
            int k = lane + kc*32;
            float acc = 0.f;
            #pragma unroll
            for (int d = 0; d < 16; d++)
                acc += q[d]*WekT[(h*16 + d)*129 + k];
            g_P[((size_t)(nb0+nl)*8 + h)*128 + k] = acc;
        }
    }
}

// ---------------- multi-slot [M,128]@[128,128] split-bf16 GEMM (QKV) ----------------
#define GEMM_SMEM (4*128*136*2)
__global__ __launch_bounds__(512) void gemm_multi(
    const float* __restrict__ A, int slot0, int nslots,
    float* __restrict__ O0, float* __restrict__ O1, float* __restrict__ O2,
    const float* __restrict__ bias, int M)
{
    extern __shared__ char sm[];
    bf16* sAh = (bf16*)sm;
    bf16* sAl = sAh + 128*136;
    bf16* sWh = sAl + 128*136;
    bf16* sWl = sWh + 128*136;
    float* sC = (float*)(sm + 2*128*136*2);

    const int tid = threadIdx.x;
    const int m0  = blockIdx.x*128;

    for (int i = tid; i < 4096; i += 512) {
        int r = i>>5, c4 = (i&31)*4;
        float4 v = make_float4(0.f,0.f,0.f,0.f);
        if (m0 + r < M) v = *(const float4*)(A + (size_t)(m0+r)*128 + c4);
        bf16 h0=__float2bfloat16(v.x), h1=__float2bfloat16(v.y);
        bf16 h2=__float2bfloat16(v.z), h3=__float2bfloat16(v.w);
        __nv_bfloat162 hh0; hh0.x=h0; hh0.y=h1;
        __nv_bfloat162 hh1; hh1.x=h2; hh1.y=h3;
        *(__nv_bfloat162*)(sAh + r*136 + c4)     = hh0;
        *(__nv_bfloat162*)(sAh + r*136 + c4 + 2) = hh1;
        __nv_bfloat162 ll0, ll1;
        ll0.x=__float2bfloat16(v.x-__bfloat162float(h0));
        ll0.y=__float2bfloat16(v.y-__bfloat162float(h1));
        ll1.x=__float2bfloat16(v.z-__bfloat162float(h2));
        ll1.y=__float2bfloat16(v.w-__bfloat162float(h3));
        *(__nv_bfloat162*)(sAl + r*136 + c4)     = ll0;
        *(__nv_bfloat162*)(sAl + r*136 + c4 + 2) = ll1;
    }

    const int w  = tid>>5;
    const int wr = w>>2;
    const int wc = w&3;

    for (int s = 0; s < nslots; s++) {
        const bf16* Wh = g_w_hi + (size_t)(slot0+s)*16384;
        const bf16* Wl = g_w_lo + (size_t)(slot0+s)*16384;
        for (int i = tid; i < 1024; i += 512) {
            int r = i>>3, c16 = (i&7)*16;
            *(uint4*)(sWh + r*136 + c16)     = *(const uint4*)(Wh + r*128 + c16);
            *(uint4*)(sWh + r*136 + c16 + 8) = *(const uint4*)(Wh + r*128 + c16 + 8);
            *(uint4*)(sWl + r*136 + c16)     = *(const uint4*)(Wl + r*128 + c16);
            *(uint4*)(sWl + r*136 + c16 + 8) = *(const uint4*)(Wl + r*128 + c16 + 8);
        }
        __syncthreads();

        wmma::fragment<wmma::accumulator,16,16,16,float> acc[2][2];
        #pragma unroll
        for (int i=0;i<2;i++)
            #pragma unroll
            for (int j=0;j<2;j++) wmma::fill_fragment(acc[i][j], 0.f);

        #pragma unroll
        for (int kk=0; kk<8; kk++) {
            wmma::fragment<wmma::matrix_a,16,16,16,bf16,wmma::row_major> ah[2], al[2];
            #pragma unroll
            for (int mt=0; mt<2; mt++) {
                wmma::load_matrix_sync(ah[mt], sAh + (wr*32+mt*16)*136 + kk*16, 136);
                wmma::load_matrix_sync(al[mt], sAl + (wr*32+mt*16)*136 + kk*16, 136);
            }
            #pragma unroll
            for (int nt=0; nt<2; nt++) {
                wmma::fragment<wmma::matrix_b,16,16,16,bf16,wmma::row_major> bh, bl;
                wmma::load_matrix_sync(bh, sWh + kk*16*136 + wc*32 + nt*16, 136);
                wmma::load_matrix_sync(bl, sWl + kk*16*136 + wc*32 + nt*16, 136);
                #pragma unroll
                for (int mt=0; mt<2; mt++) {
                    wmma::mma_sync(acc[mt][nt], ah[mt], bh, acc[mt][nt]);
                    wmma::mma_sync(acc[mt][nt], ah[mt], bl, acc[mt][nt]);
                    wmma::mma_sync(acc[mt][nt], al[mt], bh, acc[mt][nt]);
                }
            }
        }
        __syncthreads();
        #pragma unroll
        for (int mt=0; mt<2; mt++)
            #pragma unroll
            for (int nt=0; nt<2; nt++)
                wmma::store_matrix_sync(sC + (wr*32+mt*16)*132 + wc*32 + nt*16, acc[mt][nt], 132, wmma::mem_row_major);
        __syncthreads();

        float* C = (s == 0) ? O0 : ((s == 1) ? O1 : O2);
        for (int i = tid; i < 4096; i += 512) {
            int r = i>>5, c4 = (i&31)*4;
            if (m0 + r < M) {
                float4 v = *(const float4*)(sC + r*132 + c4);
                if (bias) { v.x += bias[c4]; v.y += bias[c4+1]; v.z += bias[c4+2]; v.w += bias[c4+3]; }
                *(float4*)(C + (size_t)(m0+r)*128 + c4) = v;
            }
        }
        __syncthreads();
    }
}

// ---------------- output GEMM: out = [aggv | z] @ Wbig + bout, K=1152 ----------------
__global__ __launch_bounds__(512) void gemm_out(
    const float* __restrict__ aggv, const float* __restrict__ z,
    float* __restrict__ out, const float* __restrict__ bias, int M)
{
    extern __shared__ char sm[];
    bf16* sAh = (bf16*)sm;
    bf16* sAl = sAh + 128*136;
    bf16* sWh = sAl + 128*136;
    bf16* sWl = sWh + 128*136;
    float* sC = (float*)(sm + 2*128*136*2);

    const int tid = threadIdx.x;
    const int m0  = blockIdx.x*128;
    const int w   = tid>>5;
    const int wr  = w>>2;
    const int wc  = w&3;

    wmma::fragment<wmma::accumulator,16,16,16,float> acc[2][2];
    #pragma unroll
    for (int i=0;i<2;i++)
        #pragma unroll
        for (int j=0;j<2;j++) wmma::fill_fragment(acc[i][j], 0.f);

    for (int ch = 0; ch < 9; ch++) {
        // A chunk [128 x 128] fp32 -> split
        for (int i = tid; i < 4096; i += 512) {
            int r = i>>5, c4 = (i&31)*4;
            float4 v = make_float4(0.f,0.f,0.f,0.f);
            if (m0 + r < M)
                v = (ch == 0) ? *(const float4*)(aggv + (size_t)(m0+r)*128 + c4)
                              : *(const float4*)(z + (size_t)(m0+r)*1024 + (ch-1)*128 + c4);
            bf16 h0=__float2bfloat16(v.x), h1=__float2bfloat16(v.y);
            bf16 h2=__float2bfloat16(v.z), h3=__float2bfloat16(v.w);
            __nv_bfloat162 hh0; hh0.x=h0; hh0.y=h1;
            __nv_bfloat162 hh1; hh1.x=h2; hh1.y=h3;
            *(__nv_bfloat162*)(sAh + r*136 + c4)     = hh0;
            *(__nv_bfloat162*)(sAh + r*136 + c4 + 2) = hh1;
            __nv_bfloat162 ll0, ll1;
            ll0.x=__float2bfloat16(v.x-__bfloat162float(h0));
            ll0.y=__float2bfloat16(v.y-__bfloat162float(h1));
            ll1.x=__float2bfloat16(v.z-__bfloat162float(h2));
            ll1.y=__float2bfloat16(v.w-__bfloat162float(h3));
            *(__nv_bfloat162*)(sAl + r*136 + c4)     = ll0;
            *(__nv_bfloat162*)(sAl + r*136 + c4 + 2) = ll1;
        }
        // W chunk
        for (int i = tid; i < 1024; i += 512) {
            int r = i>>3, c16 = (i&7)*16;
            const bf16* Wh = g_wbig_hi + (size_t)(ch*128 + r)*128;
            const bf16* Wl = g_wbig_lo + (size_t)(ch*128 + r)*128;
            *(uint4*)(sWh + r*136 + c16)     = *(const uint4*)(Wh + c16);
            *(uint4*)(sWh + r*136 + c16 + 8) = *(const uint4*)(Wh + c16 + 8);
            *(uint4*)(sWl + r*136 + c16)     = *(const uint4*)(Wl + c16);
            *(uint4*)(sWl + r*136 + c16 + 8) = *(const uint4*)(Wl + c16 + 8);
        }
        __syncthreads();

        #pragma unroll
        for (int kk=0; kk<8; kk++) {
            wmma::fragment<wmma::matrix_a,16,16,16,bf16,wmma::row_major> ah[2], al[2];
            #pragma unroll
            for (int mt=0; mt<2; mt++) {
                wmma::load_matrix_sync(ah[mt], sAh + (wr*32+mt*16)*136 + kk*16, 136);
                wmma::load_matrix_sync(al[mt], sAl + (wr*32+mt*16)*136 + kk*16, 136);
            }
            #pragma unroll
            for (int nt=0; nt<2; nt++) {
                wmma::fragment<wmma::matrix_b,16,16,16,bf16,wmma::row_major> bh, bl;
                wmma::load_matrix_sync(bh, sWh + kk*16*136 + wc*32 + nt*16, 136);
                wmma::load_matrix_sync(bl, sWl + kk*16*136 + wc*32 + nt*16, 136);
                #pragma unroll
                for (int mt=0; mt<2; mt++) {
                    wmma::mma_sync(acc[mt][nt], ah[mt], bh, acc[mt][nt]);
                    wmma::mma_sync(acc[mt][nt], ah[mt], bl, acc[mt][nt]);
                    wmma::mma_sync(acc[mt][nt], al[mt], bh, acc[mt][nt]);
                }
            }
        }
        __syncthreads();
    }

    #pragma unroll
    for (int mt=0; mt<2; mt++)
        #pragma unroll
        for (int nt=0; nt<2; nt++)
            wmma::store_matrix_sync(sC + (wr*32+mt*16)*132 + wc*32 + nt*16, acc[mt][nt], 132, wmma::mem_row_major);
    __syncthreads();

    for (int i = tid; i < 4096; i += 512) {
        int r = i>>5, c4 = (i&31)*4;
        if (m0 + r < M) {
            float4 v = *(const float4*)(sC + r*132 + c4);
            v.x += bias[c4]; v.y += bias[c4+1]; v.z += bias[c4+2]; v.w += bias[c4+3];
            *(float4*)(out + (size_t)(m0+r)*128 + c4) = v;
        }
    }
}

// ---------------- edge kernel: scores/softmax/z/aggv, all fp32 scalar ----------------
#define EO_E    0                      // 128*132*4 = 67584
#define EO_KS   67584                  // 24*132*4  = 12672
#define EO_V    80256                  // 12672
#define EO_SE   92928                  // 4096
#define EO_SA   97024                  // 4096
#define EO_DST  101120                 // 512
#define EO_WEXP 101632                 // 256
#define EDGE_SMEM 101888

__global__ __launch_bounds__(256, 2) void edge_kernel(
    const float* __restrict__ edges, const int* __restrict__ eidx,
    const float* __restrict__ Wexp)
{
    extern __shared__ char sm[];
    float* Es    = (float*)(sm + EO_E);
    float* KSs   = (float*)(sm + EO_KS);
    float* Vs    = (float*)(sm + EO_V);
    float* SE    = (float*)(sm + EO_SE);
    float* SA    = (float*)(sm + EO_SA);
    int*   DSTs  = (int*)  (sm + EO_DST);
    float* WEXPs = (float*)(sm + EO_WEXP);

    const int tid  = threadIdx.x;
    const int w    = tid>>5;
    const int lane = tid&31;
    const int t    = blockIdx.x;
    const int n0   = t*8;
    const int e0   = t*128;

    // loads: edge tile (fp32, no split), dst, KS/V rows n0+1..n0+23, Wexp
    for (int i = tid; i < 4096; i += 256) {
        int r = i>>5, c4 = (i&31)*4;
        *(float4*)(Es + r*132 + c4) = *(const float4*)(edges + (size_t)(e0+r)*128 + c4);
    }
    if (tid < 128) DSTs[tid] = eidx[NE + e0 + tid];
    for (int i = tid; i < 736; i += 256) {
        int r = i>>5, c4 = (i&31)*4;
        int nd = n0 + 1 + r;
        if (nd >= NN) nd -= NN;
        *(float4*)(KSs + r*132 + c4) = *(const float4*)(g_KS + (size_t)nd*128 + c4);
        *(float4*)(Vs  + r*132 + c4) = *(const float4*)(g_V  + (size_t)nd*128 + c4);
    }
    if (tid < 64) WEXPs[tid] = Wexp[tid];

    // per-lane P and Q (independent of smem)
    const int h  = lane>>2;
    const int kq = (lane&3)*4;
    const int node = n0 + w;
    float4 Pr[8];
    #pragma unroll
    for (int i = 0; i < 8; i++)
        Pr[i] = *(const float4*)(g_P + ((size_t)node*8 + h)*128 + kq + i*16);
    float4 Qr = *(const float4*)(g_Q + (size_t)node*128 + h*16 + kq);
    __syncthreads();

    // local rows of dst in KS/V tiles (always in [0,22] by construction)
    int rl[16];
    #pragma unroll
    for (int e = 0; e < 16; e++) {
        int r = DSTs[w*16 + e] - (n0 + 1);
        if (r < 0) r += NN;
        rl[e] = r;
    }

    // scores: s[e,h] = Q.KS(dst) + E(e,:).P(src,h,:)
    #pragma unroll
    for (int e = 0; e < 16; e++) {
        const float* er = Es + (w*16 + e)*132;
        float s = 0.f;
        #pragma unroll
        for (int i = 0; i < 8; i++) {
            float4 E4 = *(const float4*)(er + kq + i*16);
            s += E4.x*Pr[i].x + E4.y*Pr[i].y + E4.z*Pr[i].z + E4.w*Pr[i].w;
        }
        float4 K4 = *(const float4*)(KSs + rl[e]*132 + h*16 + kq);
        s += Qr.x*K4.x + Qr.y*K4.y + Qr.z*K4.z + Qr.w*K4.w;
        s += __shfl_xor_sync(0xffffffffu, s, 1);
        s += __shfl_xor_sync(0xffffffffu, s, 2);
        if ((lane&3) == 0) SE[(w*16 + e)*8 + h] = s;
    }
    __syncthreads();

    // head expansion SA = SE @ Wexp
    for (int i = tid; i < 1024; i += 256) {
        int e = i>>3, he = i&7;
        float v = 0.f;
        #pragma unroll
        for (int hh = 0; hh < 8; hh++) v += SE[e*8 + hh]*WEXPs[hh*8 + he];
        SA[i] = v;
    }
    __syncthreads();

    // segment softmax per (node, he)
    if (tid < 64) {
        int nd = tid>>3, he = tid&7;
        int base = nd*16;
        float m = -1e30f;
        #pragma unroll
        for (int j = 0; j < 16; j++) m = fmaxf(m, SA[(base+j)*8 + he]);
        float ex[16], su = 0.f;
        #pragma unroll
        for (int j = 0; j < 16; j++) { ex[j] = __expf(SA[(base+j)*8 + he] - m); su += ex[j]; }
        float inv = 1.f/su;
        #pragma unroll
        for (int j = 0; j < 16; j++) SA[(base+j)*8 + he] = ex[j]*inv;
    }
    __syncthreads();

    // z[node][h][k] = sum_e a[e,h]*E[e,k]
    float4 zac[8];
    #pragma unroll
    for (int i = 0; i < 8; i++) zac[i] = make_float4(0.f,0.f,0.f,0.f);
    #pragma unroll
    for (int e = 0; e < 16; e++) {
        float a = SA[(w*16 + e)*8 + h];
        const float* er = Es + (w*16 + e)*132;
        #pragma unroll
        for (int i = 0; i < 8; i++) {
            float4 E4 = *(const float4*)(er + kq + i*16);
            zac[i].x += a*E4.x; zac[i].y += a*E4.y;
            zac[i].z += a*E4.z; zac[i].w += a*E4.w;
        }
    }
    #pragma unroll
    for (int i = 0; i < 8; i++)
        *(float4*)(g_z + (size_t)node*1024 + h*128 + kq + i*16) = zac[i];

    // aggv[node][c] = sum_e a[e,h(c)]*V[dst,c]
    #pragma unroll
    for (int cc = 0; cc < 4; cc++) {
        int c = lane + cc*32;
        int hc = c>>4;
        float acc = 0.f;
        #pragma unroll
        for (int e = 0; e < 16; e++)
            acc += SA[(w*16 + e)*8 + hc] * Vs[rl[e]*132 + c];
        g_aggv[(size_t)node*128 + c] = acc;
    }
}

// ---------------- launch ----------------
extern "C" void kernel_launch(void* const* d_in, const int* in_sizes, int n_in,
                              void* d_out, int out_size)
{
    const float* x    = (const float*)d_in[0];
    const float* edges= (const float*)d_in[1];
    const int*   eidx = (const int*)  d_in[2];
    const float* Wq   = (const float*)d_in[3];
    const float* Wk   = (const float*)d_in[4];
    const float* Wv   = (const float*)d_in[5];
    const float* Wek  = (const float*)d_in[6];
    const float* Wev  = (const float*)d_in[7];
    const float* Wexp = (const float*)d_in[8];
    const float* Wout = (const float*)d_in[9];
    const float* bout = (const float*)d_in[10];
    float* out = (float*)d_out;

    float *Qg, *KSg, *Vg, *zg, *aggvg;
    cudaGetSymbolAddress((void**)&Qg,    g_Q);
    cudaGetSymbolAddress((void**)&KSg,   g_KS);
    cudaGetSymbolAddress((void**)&Vg,    g_V);
    cudaGetSymbolAddress((void**)&zg,    g_z);
    cudaGetSymbolAddress((void**)&aggvg, g_aggv);

    cudaFuncSetAttribute(gemm_multi,  cudaFuncAttributeMaxDynamicSharedMemorySize, GEMM_SMEM);
    cudaFuncSetAttribute(gemm_out,    cudaFuncAttributeMaxDynamicSharedMemorySize, GEMM_SMEM);
    cudaFuncSetAttribute(pkern,       cudaFuncAttributeMaxDynamicSharedMemorySize, PK_SMEM);
    cudaFuncSetAttribute(edge_kernel, cudaFuncAttributeMaxDynamicSharedMemorySize, EDGE_SMEM);

    // weight prep (independent of x)
    wsplit_kernel<<<dim3(64,3),256>>>(Wq, Wk, Wv);
    wcomb_kernel<<<576,256>>>(Wev, Wout);

    // Q / KS / V
    gemm_multi<<<(NN+127)/128,512,GEMM_SMEM>>>(x, 0, 3, Qg, KSg, Vg, nullptr, NN);

    // P[n,h,k]
    pkern<<<NN/16,512,PK_SMEM>>>(Wek);

    // fused edge pass: scores -> expansion -> softmax -> z + aggv
    edge_kernel<<<NT8,256,EDGE_SMEM>>>(edges, eidx, Wexp);

    // out = aggv@(-Wout) + z@(-Wcomb) + bout
    gemm_out<<<(NN+127)/128,512,GEMM_SMEM>>>(aggvg, zg, out, bout, NN);
}

// round 7
// speedup vs baseline: 1.5243x; 1.2687x over previous
#include <cuda_runtime.h>
#include <cuda_bf16.h>
#include <mma.h>
#include <cstdint>

using namespace nvcuda;
typedef __nv_bfloat16 bf16;

#define NN   20000
#define DEGC 16
#define NE   (NN*DEGC)     // 320000
#define DIMC 128
#define SCALEC 0.25f       // HD^-0.5, HD=16
#define NT8  2500          // edge tiles of 8 nodes / 128 edges

// ---------------- scratch (__device__ globals; no allocation allowed) ----------------
__device__ float g_Q   [NN*DIMC];
__device__ float g_KS  [NN*DIMC];
__device__ float g_V   [NN*DIMC];
__device__ float g_P   [NN*8*DIMC];   // P[n][h][k] = sum_{d in h} Q[n,d]*Wek[k,d]*S
__device__ float g_z   [NN*8*DIMC];   // z[n][h][k] = sum_{e in n} a[e,h]*E[e,k]
__device__ float g_aggv[NN*DIMC];     // sum_e a[e,h(c)]*V[dst,c]  (+ y added by ykern)
__device__ float g_WekT[DIMC*DIMC];   // WekT[d][k] = Wek[k][d]*S
// weight slots hi/lo, row-major [k][n]: 0=Wq 1=Wk*S 2=Wv 3=-Wout
__device__ bf16  g_w_hi[4*DIMC*DIMC];
__device__ bf16  g_w_lo[4*DIMC*DIMC];

// ---------------- weight split: 4 slots ----------------
__global__ void wsplit_kernel(const float* __restrict__ w0, const float* __restrict__ w1,
                              const float* __restrict__ w2, const float* __restrict__ w3)
{
    const float* srcs[4] = {w0, w1, w2, w3};
    const float  scl [4] = {1.f, SCALEC, 1.f, -1.f};
    int s = blockIdx.y;
    int i = blockIdx.x*256 + threadIdx.x;
    float v = srcs[s][i] * scl[s];
    bf16 h = __float2bfloat16(v);
    g_w_hi[s*16384 + i] = h;
    g_w_lo[s*16384 + i] = __float2bfloat16(v - __bfloat162float(h));
}

// ---------------- WekT transpose (once) ----------------
__global__ void tkern(const float* __restrict__ Wek)
{
    int i = blockIdx.x*256 + threadIdx.x;   // 16384
    int d = i>>7, k = i&127;
    g_WekT[i] = Wek[k*128 + d] * SCALEC;
}

// ---------------- P precompute: block = 64 nodes, warp = 4 nodes ----------------
#define PK_SMEM (128*128*4 + 64*128*4)   // WekT 64KB + Qs 32KB = 96KB
__global__ __launch_bounds__(512) void pkern()
{
    extern __shared__ float smf[];
    float* WT = smf;                 // [d][k] stride 128
    float* Qs = smf + 16384;         // [64][128]

    const int tid = threadIdx.x;
    const int nb0 = blockIdx.x*64;

    for (int i = tid; i < 4096; i += 512)
        *(float4*)(WT + i*4) = *(const float4*)(g_WekT + i*4);
    for (int i = tid; i < 2048; i += 512) {
        int n = nb0 + (i>>5);
        float4 v = make_float4(0.f,0.f,0.f,0.f);
        if (n < NN) v = *(const float4*)(g_Q + (size_t)n*128 + (i&31)*4);
        *(float4*)(Qs + (i>>5)*128 + (i&31)*4) = v;
    }
    __syncthreads();

    const int w = tid>>5, lane = tid&31;
    const int nl0 = w*4;
    const int k4  = lane*4;

    #pragma unroll
    for (int h = 0; h < 8; h++) {
        float4 acc[4];
        #pragma unroll
        for (int j = 0; j < 4; j++) acc[j] = make_float4(0.f,0.f,0.f,0.f);
        #pragma unroll
        for (int d = 0; d < 16; d++) {
            float4 w4 = *(const float4*)(WT + (h*16 + d)*128 + k4);
            #pragma unroll
            for (int j = 0; j < 4; j++) {
                float qv = Qs[(nl0 + j)*128 + h*16 + d];
                acc[j].x += qv*w4.x; acc[j].y += qv*w4.y;
                acc[j].z += qv*w4.z; acc[j].w += qv*w4.w;
            }
        }
        #pragma unroll
        for (int j = 0; j < 4; j++) {
            int n = nb0 + nl0 + j;
            if (n < NN)
                *(float4*)(g_P + ((size_t)n*8 + h)*128 + k4) = acc[j];
        }
    }
}

// ---------------- y: aggv += z @ Wev (block-diagonal); block = 64 nodes ----------------
#define YK_SMEM (128*128*4)   // Wev 64KB
__global__ __launch_bounds__(512) void ykern(const float* __restrict__ Wev)
{
    extern __shared__ float WV[];    // [k][c] natural
    const int tid = threadIdx.x;
    for (int i = tid; i < 4096; i += 512)
        *(float4*)(WV + i*4) = *(const float4*)(Wev + i*4);
    __syncthreads();

    const int w = tid>>5, lane = tid&31;
    const int nb = blockIdx.x*64 + w*4;
    const int c4 = lane*4;
    const int h  = lane>>2;

    float4 acc[4];
    #pragma unroll
    for (int j = 0; j < 4; j++) acc[j] = make_float4(0.f,0.f,0.f,0.f);

    const int jmax = (nb + 4 <= NN) ? 4 : (nb < NN ? NN - nb : 0);
    const float* zr0 = g_z + (size_t)nb*1024 + h*128;

    for (int kb = 0; kb < 32; kb++) {
        float4 z4[4];
        #pragma unroll
        for (int j = 0; j < 4; j++)
            z4[j] = (j < jmax) ? *(const float4*)(zr0 + j*1024 + kb*4)
                               : make_float4(0.f,0.f,0.f,0.f);
        #pragma unroll
        for (int kk = 0; kk < 4; kk++) {
            float4 w4 = *(const float4*)(WV + (kb*4 + kk)*128 + c4);
            #pragma unroll
            for (int j = 0; j < 4; j++) {
                float zb = (kk==0) ? z4[j].x : (kk==1) ? z4[j].y : (kk==2) ? z4[j].z : z4[j].w;
                acc[j].x += zb*w4.x; acc[j].y += zb*w4.y;
                acc[j].z += zb*w4.z; acc[j].w += zb*w4.w;
            }
        }
    }
    #pragma unroll
    for (int j = 0; j < 4; j++) {
        if (j < jmax) {
            float* ar = g_aggv + (size_t)(nb + j)*128 + c4;
            float4 av = *(const float4*)ar;
            av.x += acc[j].x; av.y += acc[j].y; av.z += acc[j].z; av.w += acc[j].w;
            *(float4*)ar = av;
        }
    }
}

// ---------------- multi-slot [M,128]@[128,128] split-bf16 GEMM ----------------
#define GEMM_SMEM (4*128*136*2)
__global__ __launch_bounds__(512) void gemm_multi(
    const float* __restrict__ A, int slot0, int nslots,
    float* __restrict__ O0, float* __restrict__ O1, float* __restrict__ O2,
    const float* __restrict__ bias, int M)
{
    extern __shared__ char sm[];
    bf16* sAh = (bf16*)sm;
    bf16* sAl = sAh + 128*136;
    bf16* sWh = sAl + 128*136;
    bf16* sWl = sWh + 128*136;
    float* sC = (float*)(sm + 2*128*136*2);

    const int tid = threadIdx.x;
    const int m0  = blockIdx.x*128;

    for (int i = tid; i < 4096; i += 512) {
        int r = i>>5, c4 = (i&31)*4;
        float4 v = make_float4(0.f,0.f,0.f,0.f);
        if (m0 + r < M) v = *(const float4*)(A + (size_t)(m0+r)*128 + c4);
        bf16 h0=__float2bfloat16(v.x), h1=__float2bfloat16(v.y);
        bf16 h2=__float2bfloat16(v.z), h3=__float2bfloat16(v.w);
        __nv_bfloat162 hh0; hh0.x=h0; hh0.y=h1;
        __nv_bfloat162 hh1; hh1.x=h2; hh1.y=h3;
        *(__nv_bfloat162*)(sAh + r*136 + c4)     = hh0;
        *(__nv_bfloat162*)(sAh + r*136 + c4 + 2) = hh1;
        __nv_bfloat162 ll0, ll1;
        ll0.x=__float2bfloat16(v.x-__bfloat162float(h0));
        ll0.y=__float2bfloat16(v.y-__bfloat162float(h1));
        ll1.x=__float2bfloat16(v.z-__bfloat162float(h2));
        ll1.y=__float2bfloat16(v.w-__bfloat162float(h3));
        *(__nv_bfloat162*)(sAl + r*136 + c4)     = ll0;
        *(__nv_bfloat162*)(sAl + r*136 + c4 + 2) = ll1;
    }

    const int w  = tid>>5;
    const int wr = w>>2;
    const int wc = w&3;

    for (int s = 0; s < nslots; s++) {
        const bf16* Wh = g_w_hi + (size_t)(slot0+s)*16384;
        const bf16* Wl = g_w_lo + (size_t)(slot0+s)*16384;
        for (int i = tid; i < 1024; i += 512) {
            int r = i>>3, c16 = (i&7)*16;
            *(uint4*)(sWh + r*136 + c16)     = *(const uint4*)(Wh + r*128 + c16);
            *(uint4*)(sWh + r*136 + c16 + 8) = *(const uint4*)(Wh + r*128 + c16 + 8);
            *(uint4*)(sWl + r*136 + c16)     = *(const uint4*)(Wl + r*128 + c16);
            *(uint4*)(sWl + r*136 + c16 + 8) = *(const uint4*)(Wl + r*128 + c16 + 8);
        }
        __syncthreads();

        wmma::fragment<wmma::accumulator,16,16,16,float> acc[2][2];
        #pragma unroll
        for (int i=0;i<2;i++)
            #pragma unroll
            for (int j=0;j<2;j++) wmma::fill_fragment(acc[i][j], 0.f);

        #pragma unroll
        for (int kk=0; kk<8; kk++) {
            wmma::fragment<wmma::matrix_a,16,16,16,bf16,wmma::row_major> ah[2], al[2];
            #pragma unroll
            for (int mt=0; mt<2; mt++) {
                wmma::load_matrix_sync(ah[mt], sAh + (wr*32+mt*16)*136 + kk*16, 136);
                wmma::load_matrix_sync(al[mt], sAl + (wr*32+mt*16)*136 + kk*16, 136);
            }
            #pragma unroll
            for (int nt=0; nt<2; nt++) {
                wmma::fragment<wmma::matrix_b,16,16,16,bf16,wmma::row_major> bh, bl;
                wmma::load_matrix_sync(bh, sWh + kk*16*136 + wc*32 + nt*16, 136);
                wmma::load_matrix_sync(bl, sWl + kk*16*136 + wc*32 + nt*16, 136);
                #pragma unroll
                for (int mt=0; mt<2; mt++) {
                    wmma::mma_sync(acc[mt][nt], ah[mt], bh, acc[mt][nt]);
                    wmma::mma_sync(acc[mt][nt], ah[mt], bl, acc[mt][nt]);
                    wmma::mma_sync(acc[mt][nt], al[mt], bh, acc[mt][nt]);
                }
            }
        }
        __syncthreads();
        #pragma unroll
        for (int mt=0; mt<2; mt++)
            #pragma unroll
            for (int nt=0; nt<2; nt++)
                wmma::store_matrix_sync(sC + (wr*32+mt*16)*132 + wc*32 + nt*16, acc[mt][nt], 132, wmma::mem_row_major);
        __syncthreads();

        float* C = (s == 0) ? O0 : ((s == 1) ? O1 : O2);
        for (int i = tid; i < 4096; i += 512) {
            int r = i>>5, c4 = (i&31)*4;
            if (m0 + r < M) {
                float4 v = *(const float4*)(sC + r*132 + c4);
                if (bias) { v.x += bias[c4]; v.y += bias[c4+1]; v.z += bias[c4+2]; v.w += bias[c4+3]; }
                *(float4*)(C + (size_t)(m0+r)*128 + c4) = v;
            }
        }
        __syncthreads();
    }
}

// ---------------- edge kernel: scores/softmax/z/aggv, all fp32 scalar ----------------
#define EO_E    0                      // 128*132*4 = 67584
#define EO_KS   67584                  // 24*132*4  = 12672
#define EO_V    80256                  // 12672
#define EO_SE   92928                  // 4096
#define EO_SA   97024                  // 4096
#define EO_DST  101120                 // 512
#define EO_WEXP 101632                 // 256
#define EDGE_SMEM 101888

__global__ __launch_bounds__(256, 2) void edge_kernel(
    const float* __restrict__ edges, const int* __restrict__ eidx,
    const float* __restrict__ Wexp)
{
    extern __shared__ char sm[];
    float* Es    = (float*)(sm + EO_E);
    float* KSs   = (float*)(sm + EO_KS);
    float* Vs    = (float*)(sm + EO_V);
    float* SE    = (float*)(sm + EO_SE);
    float* SA    = (float*)(sm + EO_SA);
    int*   DSTs  = (int*)  (sm + EO_DST);
    float* WEXPs = (float*)(sm + EO_WEXP);

    const int tid  = threadIdx.x;
    const int w    = tid>>5;
    const int lane = tid&31;
    const int t    = blockIdx.x;
    const int n0   = t*8;
    const int e0   = t*128;

    for (int i = tid; i < 4096; i += 256) {
        int r = i>>5, c4 = (i&31)*4;
        *(float4*)(Es + r*132 + c4) = *(const float4*)(edges + (size_t)(e0+r)*128 + c4);
    }
    if (tid < 128) DSTs[tid] = eidx[NE + e0 + tid];
    for (int i = tid; i < 736; i += 256) {
        int r = i>>5, c4 = (i&31)*4;
        int nd = n0 + 1 + r;
        if (nd >= NN) nd -= NN;
        *(float4*)(KSs + r*132 + c4) = *(const float4*)(g_KS + (size_t)nd*128 + c4);
        *(float4*)(Vs  + r*132 + c4) = *(const float4*)(g_V  + (size_t)nd*128 + c4);
    }
    if (tid < 64) WEXPs[tid] = Wexp[tid];

    const int h  = lane>>2;
    const int kq = (lane&3)*4;
    const int node = n0 + w;
    float4 Pr[8];
    #pragma unroll
    for (int i = 0; i < 8; i++)
        Pr[i] = *(const float4*)(g_P + ((size_t)node*8 + h)*128 + kq + i*16);
    float4 Qr = *(const float4*)(g_Q + (size_t)node*128 + h*16 + kq);
    __syncthreads();

    int rl[16];
    #pragma unroll
    for (int e = 0; e < 16; e++) {
        int r = DSTs[w*16 + e] - (n0 + 1);
        if (r < 0) r += NN;
        rl[e] = r;
    }

    #pragma unroll
    for (int e = 0; e < 16; e++) {
        const float* er = Es + (w*16 + e)*132;
        float s = 0.f;
        #pragma unroll
        for (int i = 0; i < 8; i++) {
            float4 E4 = *(const float4*)(er + kq + i*16);
            s += E4.x*Pr[i].x + E4.y*Pr[i].y + E4.z*Pr[i].z + E4.w*Pr[i].w;
        }
        float4 K4 = *(const float4*)(KSs + rl[e]*132 + h*16 + kq);
        s += Qr.x*K4.x + Qr.y*K4.y + Qr.z*K4.z + Qr.w*K4.w;
        s += __shfl_xor_sync(0xffffffffu, s, 1);
        s += __shfl_xor_sync(0xffffffffu, s, 2);
        if ((lane&3) == 0) SE[(w*16 + e)*8 + h] = s;
    }
    __syncthreads();

    for (int i = tid; i < 1024; i += 256) {
        int e = i>>3, he = i&7;
        float v = 0.f;
        #pragma unroll
        for (int hh = 0; hh < 8; hh++) v += SE[e*8 + hh]*WEXPs[hh*8 + he];
        SA[i] = v;
    }
    __syncthreads();

    if (tid < 64) {
        int nd = tid>>3, he = tid&7;
        int base = nd*16;
        float m = -1e30f;
        #pragma unroll
        for (int j = 0; j < 16; j++) m = fmaxf(m, SA[(base+j)*8 + he]);
        float ex[16], su = 0.f;
        #pragma unroll
        for (int j = 0; j < 16; j++) { ex[j] = __expf(SA[(base+j)*8 + he] - m); su += ex[j]; }
        float inv = 1.f/su;
        #pragma unroll
        for (int j = 0; j < 16; j++) SA[(base+j)*8 + he] = ex[j]*inv;
    }
    __syncthreads();

    float4 zac[8];
    #pragma unroll
    for (int i = 0; i < 8; i++) zac[i] = make_float4(0.f,0.f,0.f,0.f);
    #pragma unroll
    for (int e = 0; e < 16; e++) {
        float a = SA[(w*16 + e)*8 + h];
        const float* er = Es + (w*16 + e)*132;
        #pragma unroll
        for (int i = 0; i < 8; i++) {
            float4 E4 = *(const float4*)(er + kq + i*16);
            zac[i].x += a*E4.x; zac[i].y += a*E4.y;
            zac[i].z += a*E4.z; zac[i].w += a*E4.w;
        }
    }
    #pragma unroll
    for (int i = 0; i < 8; i++)
        *(float4*)(g_z + (size_t)node*1024 + h*128 + kq + i*16) = zac[i];

    #pragma unroll
    for (int cc = 0; cc < 4; cc++) {
        int c = lane + cc*32;
        int hc = c>>4;
        float acc = 0.f;
        #pragma unroll
        for (int e = 0; e < 16; e++)
            acc += SA[(w*16 + e)*8 + hc] * Vs[rl[e]*132 + c];
        g_aggv[(size_t)node*128 + c] = acc;
    }
}

// ---------------- launch ----------------
extern "C" void kernel_launch(void* const* d_in, const int* in_sizes, int n_in,
                              void* d_out, int out_size)
{
    const float* x    = (const float*)d_in[0];
    const float* edges= (const float*)d_in[1];
    const int*   eidx = (const int*)  d_in[2];
    const float* Wq   = (const float*)d_in[3];
    const float* Wk   = (const float*)d_in[4];
    const float* Wv   = (const float*)d_in[5];
    const float* Wek  = (const float*)d_in[6];
    const float* Wev  = (const float*)d_in[7];
    const float* Wexp = (const float*)d_in[8];
    const float* Wout = (const float*)d_in[9];
    const float* bout = (const float*)d_in[10];
    float* out = (float*)d_out;

    float *Qg, *KSg, *Vg, *aggvg;
    cudaGetSymbolAddress((void**)&Qg,    g_Q);
    cudaGetSymbolAddress((void**)&KSg,   g_KS);
    cudaGetSymbolAddress((void**)&Vg,    g_V);
    cudaGetSymbolAddress((void**)&aggvg, g_aggv);

    cudaFuncSetAttribute(gemm_multi,  cudaFuncAttributeMaxDynamicSharedMemorySize, GEMM_SMEM);
    cudaFuncSetAttribute(pkern,       cudaFuncAttributeMaxDynamicSharedMemorySize, PK_SMEM);
    cudaFuncSetAttribute(ykern,       cudaFuncAttributeMaxDynamicSharedMemorySize, YK_SMEM);
    cudaFuncSetAttribute(edge_kernel, cudaFuncAttributeMaxDynamicSharedMemorySize, EDGE_SMEM);

    // weight prep
    wsplit_kernel<<<dim3(64,4),256>>>(Wq, Wk, Wv, Wout);
    tkern<<<64,256>>>(Wek);

    // Q / KS / V
    gemm_multi<<<(NN+127)/128,512,GEMM_SMEM>>>(x, 0, 3, Qg, KSg, Vg, nullptr, NN);

    // P[n,h,k]
    pkern<<<(NN+63)/64,512,PK_SMEM>>>();

    // fused edge pass: scores -> expansion -> softmax -> z + aggv
    edge_kernel<<<NT8,256,EDGE_SMEM>>>(edges, eidx, Wexp);

    // aggv += z @ Wev (block-diagonal)
    ykern<<<(NN+63)/64,512,YK_SMEM>>>(Wev);

    // out = (aggv + y) @ (-Wout) + bout
    gemm_multi<<<(NN+127)/128,512,GEMM_SMEM>>>(aggvg, 3, 1, out, out, out, bout, NN);
}